// round 15
// baseline (speedup 1.0000x reference)
#include <cuda_runtime.h>
#include <cstdint>
#include <math.h>

#define Bq 8
#define Ntok 9237
#define Cc 512
#define Tt 21
#define Hh 8
#define Dd 64
#define HIDN 2048
#define M_ROWS (Bq*Ntok)          // 73896
#define EPSV 1e-5f
#define SCALEV 0.125f
#define NSEG 37                    // ceil(9237/256)
#define PSTR 72                    // smem row stride (floats): conflict-free frags
#define MTILES 578                 // ceil(73896/128)

// ---------------- static scratch (no allocations allowed) ----------------
__device__ __align__(16) float g_mean[M_ROWS];
__device__ __align__(16) float g_rstd[M_ROWS];
__device__ __align__(16) uint32_t g_Afrag[(size_t)MTILES*16*4096];  // LN'd A, tf32, fragment order
__device__ __align__(16) float g_Bfrag[1536*512];   // fragment-packed, gamma-folded, tf32
__device__ __align__(16) float g_biasc[1536];
__device__ __align__(16) float g_K0[(size_t)Bq*Hh*Ntok*Dd];
__device__ __align__(16) float g_V0[(size_t)Bq*Hh*Ntok*Dd];
__device__ __align__(16) float g_K1[(size_t)Bq*Hh*Ntok*Dd];
__device__ __align__(16) float g_q0[Bq*Tt*Cc];
__device__ __align__(16) float g_q1[Bq*Tt*Cc];
__device__ __align__(16) float g_Pacc[(size_t)Bq*Hh*NSEG*Tt*Dd];
__device__ __align__(16) float g_Psum[Bq*Hh*NSEG*Tt];
__device__ __align__(16) float g_Fsum[Bq*Hh*NSEG*Tt];
__device__ int g_cnt[Bq*Hh];

// ---------------- helpers ----------------
__device__ __forceinline__ uint32_t smem_u32(const void* p) {
    uint32_t a;
    asm("{ .reg .u64 t; cvta.to.shared.u64 t, %1; cvt.u32.u64 %0, t; }" : "=r"(a) : "l"(p));
    return a;
}
__device__ __forceinline__ uint32_t tf32r(float f) {
    uint32_t u; asm("cvt.rna.tf32.f32 %0, %1;" : "=r"(u) : "f"(f)); return u;
}
__device__ __forceinline__ void cp_async16(uint32_t smem, const void* g) {
    asm volatile("cp.async.cg.shared.global [%0], [%1], 16;" :: "r"(smem), "l"(g));
}
__device__ __forceinline__ void cp_async16z(uint32_t smem, const void* g, int szbytes) {
    asm volatile("cp.async.cg.shared.global [%0], [%1], 16, %2;"
                 :: "r"(smem), "l"(g), "r"(szbytes));
}
#define CP_COMMIT() asm volatile("cp.async.commit_group;" ::: "memory")
#define CP_WAIT0()  asm volatile("cp.async.wait_group 0;" ::: "memory")
#define CP_WAIT1()  asm volatile("cp.async.wait_group 1;" ::: "memory")

__device__ __forceinline__ void mma1688(float* c, const uint32_t* a, const uint32_t* b) {
    asm volatile(
        "mma.sync.aligned.m16n8k8.row.col.f32.tf32.tf32.f32 "
        "{%0,%1,%2,%3}, {%4,%5,%6,%7}, {%8,%9}, {%0,%1,%2,%3};"
        : "+f"(c[0]), "+f"(c[1]), "+f"(c[2]), "+f"(c[3])
        : "r"(a[0]), "r"(a[1]), "r"(a[2]), "r"(a[3]), "r"(b[0]), "r"(b[1]));
}

// ---------------- K1: prep (B frags) + LN stats + A frags + q0, one launch ----
__global__ __launch_bounds__(256) void k_prepstats(
        const float* __restrict__ x,
        const float* __restrict__ kv0_w, const float* __restrict__ kv1_w,
        const float* __restrict__ q0_w,
        const float* __restrict__ g1, const float* __restrict__ b1,
        const float* __restrict__ g3, const float* __restrict__ b3) {
    __shared__ float shbuf[128*33 + 256];
    int bid = blockIdx.x;
    int tid = threadIdx.x;
    if (bid < 1536) {
        int n = bid;
        const float *W, *g, *b; int col;
        if (n < 1024) { W = kv0_w; g = g1; b = b1; col = n; }
        else          { W = kv1_w; g = g3; b = b3; col = n - 1024; }
        int bx = n >> 7;
        int np = n & 127;
        int n8 = np >> 3, gg = np & 7;
        float partial = 0.f;
        for (int k = tid; k < 512; k += 256) {
            float w = W[(size_t)k*1024 + col] * g[k];
            int c  = k >> 5;
            int kc = k & 31;
            int ks = kc >> 3, kin = kc & 7;
            int t = kin & 3, reg = kin >> 2;
            int lane = gg*4 + t;
            size_t idx = (size_t)(bx*16 + c)*4096 + ((n8*4 + ks)*32 + lane)*2 + reg;
            g_Bfrag[idx] = __uint_as_float(tf32r(w));
            partial += b[k] * w;
        }
        float* red = shbuf;
        red[tid] = partial; __syncthreads();
        for (int s = 128; s; s >>= 1) {
            if (tid < s) red[tid] += red[tid + s];
            __syncthreads();
        }
        if (tid == 0) g_biasc[n] = red[0];
    } else if (bid < 1536 + MTILES) {
        float* ms = shbuf;
        float* rs = shbuf + 128;
        float* xs = shbuf + 256;
        int rowBase = (bid - 1536)*128;
        {
            int rl = tid >> 1;
            int row = rowBase + rl;
            int half = tid & 1;
            float s = 0.f, sq = 0.f;
            if (row < M_ROWS) {
                const float4* xr = (const float4*)(x + (size_t)row*512 + half*256);
                #pragma unroll 8
                for (int i = 0; i < 64; i++) {
                    float4 v = xr[i];
                    s  += v.x + v.y + v.z + v.w;
                    sq += v.x*v.x + v.y*v.y + v.z*v.z + v.w*v.w;
                }
            }
            s  += __shfl_xor_sync(0xffffffffu, s, 1);
            sq += __shfl_xor_sync(0xffffffffu, sq, 1);
            if (half == 0) {
                float m = s * (1.f/512.f);
                float var = sq * (1.f/512.f) - m*m;
                float rr = rsqrtf(var + EPSV);
                ms[rl] = m; rs[rl] = rr;
                if (row < M_ROWS) { g_mean[row] = m; g_rstd[row] = rr; }
            }
        }
        __syncthreads();
        uint32_t* dst = g_Afrag + (size_t)(bid - 1536)*16*4096;
        for (int c = 0; c < 16; c++) {
            #pragma unroll
            for (int it = 0; it < 4; it++) {
                int slot = tid + it*256;
                int row = slot >> 3, q = slot & 7;
                int r = rowBase + row;
                float4 v = (r < M_ROWS)
                    ? *(const float4*)(x + (size_t)r*512 + c*32 + q*4)
                    : make_float4(0,0,0,0);
                float* xp = &xs[row*33 + q*4];
                xp[0] = v.x; xp[1] = v.y; xp[2] = v.z; xp[3] = v.w;
            }
            __syncthreads();
            #pragma unroll
            for (int it = 0; it < 16; it++) {
                int f = tid + it*256;
                int reg = f & 3, lane = (f >> 2) & 31, ks = (f >> 7) & 3, mtile = f >> 9;
                int g = lane >> 2, t4 = lane & 3;
                int rl = mtile*16 + (reg & 1)*8 + g;
                int kl = ks*8 + t4 + (reg >> 1)*4;
                float v = (xs[rl*33 + kl] - ms[rl]) * rs[rl];
                dst[c*4096 + f] = tf32r(v);
            }
            __syncthreads();
        }
    } else {
        int r = bid - 1536 - MTILES;
        int b = r / Tt, t = r % Tt;
        int row = b*Ntok + t;
        float* y = shbuf;
        float* red2 = shbuf + 512;
        float v0 = x[(size_t)row*512 + tid];
        float v1 = x[(size_t)row*512 + tid + 256];
        float s = v0 + v1, sq = v0*v0 + v1*v1;
        for (int o = 16; o; o >>= 1) {
            s  += __shfl_down_sync(0xffffffffu, s, o);
            sq += __shfl_down_sync(0xffffffffu, sq, o);
        }
        int wid = tid >> 5, lane = tid & 31;
        if (lane == 0) { red2[wid] = s; red2[32 + wid] = sq; }
        __syncthreads();
        if (tid == 0) {
            float S = 0.f, SQ = 0.f;
            for (int w = 0; w < 8; w++) { S += red2[w]; SQ += red2[32 + w]; }
            float m = S * (1.f/512.f);
            red2[16] = m;
            red2[17] = rsqrtf(SQ * (1.f/512.f) - m*m + EPSV);
        }
        __syncthreads();
        float m = red2[16], rr = red2[17];
        float y0 = (v0 - m)*rr*g1[tid]       + b1[tid];
        float y1 = (v1 - m)*rr*g1[tid + 256] + b1[tid + 256];
        __syncthreads();
        y[tid] = y0;
        y[tid + 256] = y1;
        __syncthreads();
        #pragma unroll
        for (int cc = 0; cc < 2; cc++) {
            int col = tid + cc*256;
            float a0 = 0.f, a1 = 0.f, a2 = 0.f, a3 = 0.f;
            #pragma unroll 4
            for (int k = 0; k < 512; k += 4) {
                a0 = fmaf(y[k],     q0_w[(size_t)k*512 + col],       a0);
                a1 = fmaf(y[k + 1], q0_w[(size_t)(k + 1)*512 + col], a1);
                a2 = fmaf(y[k + 2], q0_w[(size_t)(k + 2)*512 + col], a2);
                a3 = fmaf(y[k + 3], q0_w[(size_t)(k + 3)*512 + col], a3);
            }
            g_q0[(size_t)r*512 + col] = (a0 + a1) + (a2 + a3);
        }
    }
}

// ---------------- K2: pure-stream tf32 mma GEMM (3-stage cp.async) ----------------
#define GEMM_SMEM (3*32768)

__global__ __launch_bounds__(256, 2) void k_gemm_mma() {
    extern __shared__ uint32_t dsmu[];

    const int tid = threadIdx.x;
    const int bx = blockIdx.x;
    const int by = blockIdx.y;
    const int colBase = bx * 128;
    const int rowBase = by * 128;

    const int lane = tid & 31, wid = tid >> 5;
    const int warp_m = wid & 1, warp_n = wid >> 1;
    const int g = lane >> 2, t4 = lane & 3;

    const uint32_t sbase = smem_u32(dsmu);
    const uint32_t* Asrc = g_Afrag + (size_t)by*16*4096;
    const uint32_t* Bsrc = (const uint32_t*)g_Bfrag + (size_t)bx*16*4096;

    auto issue = [&](int c, int s) {
        uint32_t dstA = sbase + (uint32_t)s*32768;
        const uint32_t* a = Asrc + c*4096;
        const uint32_t* b = Bsrc + c*4096;
        #pragma unroll
        for (int it = 0; it < 4; it++) {
            int off = (tid + it*256)*4;
            cp_async16(dstA + off*4, a + off);
            cp_async16(dstA + 16384 + off*4, b + off);
        }
        CP_COMMIT();
    };

    float acc[4][4][4];
    #pragma unroll
    for (int i = 0; i < 4; i++)
        #pragma unroll
        for (int j = 0; j < 4; j++)
            #pragma unroll
            for (int k = 0; k < 4; k++) acc[i][j][k] = 0.f;

    issue(0, 0); issue(1, 1);

    int s = 0;
    for (int c = 0; c < 16; c++) {
        CP_WAIT1();
        __syncthreads();
        if (c + 2 < 16) issue(c + 2, (c + 2) % 3);
        else CP_COMMIT();

        const uint32_t* Af = dsmu + s*8192;
        const uint32_t* Bf = dsmu + s*8192 + 4096;
        #pragma unroll
        for (int ks = 0; ks < 4; ks++) {
            uint32_t bfr[4][2];
            #pragma unroll
            for (int nf = 0; nf < 4; nf++) {
                int fi = (((warp_n*4 + nf)*4 + ks)*32 + lane)*2;
                uint2 bv = *(const uint2*)(Bf + fi);
                bfr[nf][0] = bv.x;
                bfr[nf][1] = bv.y;
            }
            #pragma unroll
            for (int mf = 0; mf < 4; mf++) {
                int ai = (((warp_m*4 + mf)*4 + ks)*32 + lane)*4;
                uint4 av = *(const uint4*)(Af + ai);
                uint32_t afr[4] = {av.x, av.y, av.z, av.w};
                #pragma unroll
                for (int nf = 0; nf < 4; nf++)
                    mma1688(acc[mf][nf], afr, bfr[nf]);
            }
        }
        s = (s == 2) ? 0 : s + 1;
    }

    const int region = bx >> 2;
    float* dstB = (region == 0) ? g_K0 : (region == 1) ? g_V0 : g_K1;
    float2 bias[4];
    #pragma unroll
    for (int nf = 0; nf < 4; nf++) {
        int j = colBase + warp_n*32 + nf*8 + t4*2;
        bias[nf] = *(const float2*)(g_biasc + j);
    }
    #pragma unroll
    for (int mf = 0; mf < 4; mf++) {
        #pragma unroll
        for (int hi = 0; hi < 2; hi++) {
            int r = rowBase + warp_m*64 + mf*16 + g + hi*8;
            if (r >= M_ROWS) continue;
            int bb = r / Ntok, nt = r % Ntok;
            #pragma unroll
            for (int nf = 0; nf < 4; nf++) {
                int j = colBase + warp_n*32 + nf*8 + t4*2;
                int h = (j >> 6) & 7, d = j & 63;
                float2 v;
                v.x = acc[mf][nf][hi*2 + 0] + bias[nf].x;
                v.y = acc[mf][nf][hi*2 + 1] + bias[nf].y;
                *(float2*)(dstB + (((size_t)bb*Hh + h)*Ntok + nt)*64 + d) = v;
            }
        }
    }
}

// ---------------- K3: attn0 via mma, double-buffered K/V chunk pipeline ----------
#define ATT_SMEM ((32*PSTR + 2*64*PSTR + 2*64*PSTR + 32*PSTR)*4 + 8*32*4)

__global__ __launch_bounds__(256) void k_attn0_mma() {
    extern __shared__ float sm[];
    float* Qs = sm;
    float* Ks = Qs + 32*PSTR;
    float* Vs = Ks + 2*64*PSTR;
    float* Ps = Vs + 2*64*PSTR;
    float* ws = Ps + 32*PSTR;

    int bh = blockIdx.x, seg = blockIdx.y;
    int b = bh >> 3, h = bh & 7;
    int tid = threadIdx.x;
    int lane = tid & 31, w = tid >> 5;
    int g = lane >> 2, t4 = lane & 3;

    for (int i = tid; i < 32*64; i += 256) {
        int t = i >> 6, d = i & 63;
        float v = (t < Tt) ? SCALEV * g_q0[(size_t)b*Tt*512 + h*(Tt*Dd) + t*Dd + d] : 0.f;
        Qs[t*PSTR + d] = __uint_as_float(tf32r(v));
    }

    const float* Kb = g_K0 + (size_t)bh*Ntok*64;
    const float* Vb = g_V0 + (size_t)bh*Ntok*64;
    uint32_t KsU = smem_u32(Ks), VsU = smem_u32(Vs);

    auto loadKV = [&](int ch, int buf) {
        int nc = seg*256 + ch*64;
        uint32_t kb = KsU + (uint32_t)buf*64*PSTR*4;
        uint32_t vb = VsU + (uint32_t)buf*64*PSTR*4;
        #pragma unroll
        for (int it = 0; it < 4; it++) {
            int slot = tid + it*256;
            int r = slot >> 4, c4 = (slot & 15)*4;
            int gn = nc + r;
            bool p = gn < Ntok;
            int gc = p ? gn : 0;
            int sz = p ? 16 : 0;
            cp_async16z(kb + (r*PSTR + c4)*4, Kb + (size_t)gc*64 + c4, sz);
            cp_async16z(vb + (r*PSTR + c4)*4, Vb + (size_t)gc*64 + c4, sz);
        }
        CP_COMMIT();
    };

    float o[2][4];
    #pragma unroll
    for (int m = 0; m < 2; m++)
        #pragma unroll
        for (int e = 0; e < 4; e++) o[m][e] = 0.f;
    float ssum[4] = {0.f, 0.f, 0.f, 0.f};

    loadKV(0, 0);
    for (int ch = 0; ch < 4; ch++) {
        if (ch < 3) loadKV(ch + 1, (ch + 1) & 1);
        if (ch < 3) { CP_WAIT1(); } else { CP_WAIT0(); }
        __syncthreads();

        int buf = ch & 1;
        const float* K = Ks + buf*64*PSTR;
        const float* V = Vs + buf*64*PSTR;
        int nc = seg*256 + ch*64;

        float s[2][4];
        #pragma unroll
        for (int m = 0; m < 2; m++)
            #pragma unroll
            for (int e = 0; e < 4; e++) s[m][e] = 0.f;
        #pragma unroll
        for (int ks = 0; ks < 8; ks++) {
            uint32_t bfr[2];
            bfr[0] = __float_as_uint(K[(w*8 + g)*PSTR + ks*8 + t4]);
            bfr[1] = __float_as_uint(K[(w*8 + g)*PSTR + ks*8 + t4 + 4]);
            #pragma unroll
            for (int m = 0; m < 2; m++) {
                uint32_t afr[4];
                int ab = (m*16 + g)*PSTR + ks*8 + t4;
                afr[0] = __float_as_uint(Qs[ab]);
                afr[1] = __float_as_uint(Qs[ab + 8*PSTR]);
                afr[2] = __float_as_uint(Qs[ab + 4]);
                afr[3] = __float_as_uint(Qs[ab + 8*PSTR + 4]);
                mma1688(s[m], afr, bfr);
            }
        }

        int tok0 = nc + w*8 + 2*t4;
        int tok1 = tok0 + 1;
        #pragma unroll
        for (int m = 0; m < 2; m++) {
            float e0 = __expf(s[m][0]), e1 = __expf(s[m][1]);
            float e2 = __expf(s[m][2]), e3 = __expf(s[m][3]);
            if (tok0 >= Ntok) { e0 = 0.f; e2 = 0.f; }
            if (tok1 >= Ntok) { e1 = 0.f; e3 = 0.f; }
            e0 = __uint_as_float(tf32r(e0)); e1 = __uint_as_float(tf32r(e1));
            e2 = __uint_as_float(tf32r(e2)); e3 = __uint_as_float(tf32r(e3));
            *(float2*)&Ps[(m*16 + g)*PSTR + w*8 + 2*t4]     = make_float2(e0, e1);
            *(float2*)&Ps[(m*16 + g + 8)*PSTR + w*8 + 2*t4] = make_float2(e2, e3);
            float r0 = e0 + e1, r1 = e2 + e3;
            r0 += __shfl_xor_sync(0xffffffffu, r0, 1);
            r0 += __shfl_xor_sync(0xffffffffu, r0, 2);
            r1 += __shfl_xor_sync(0xffffffffu, r1, 1);
            r1 += __shfl_xor_sync(0xffffffffu, r1, 2);
            if (t4 == 0) { ssum[m*2] += r0; ssum[m*2 + 1] += r1; }
        }
        __syncthreads();

        #pragma unroll
        for (int ks = 0; ks < 8; ks++) {
            uint32_t bfr[2];
            bfr[0] = __float_as_uint(V[(ks*8 + t4)*PSTR + w*8 + g]);
            bfr[1] = __float_as_uint(V[(ks*8 + t4 + 4)*PSTR + w*8 + g]);
            #pragma unroll
            for (int m = 0; m < 2; m++) {
                uint32_t afr[4];
                int ab = (m*16 + g)*PSTR + ks*8 + t4;
                afr[0] = __float_as_uint(Ps[ab]);
                afr[1] = __float_as_uint(Ps[ab + 8*PSTR]);
                afr[2] = __float_as_uint(Ps[ab + 4]);
                afr[3] = __float_as_uint(Ps[ab + 8*PSTR + 4]);
                mma1688(o[m], afr, bfr);
            }
        }
        __syncthreads();
    }

    if (t4 == 0) {
        ws[w*32 + g]      = ssum[0];
        ws[w*32 + g + 8]  = ssum[1];
        ws[w*32 + 16 + g] = ssum[2];
        ws[w*32 + 24 + g] = ssum[3];
    }
    __syncthreads();
    if (tid < Tt) {
        float s = 0.f;
        #pragma unroll
        for (int wq = 0; wq < 8; wq++) s += ws[wq*32 + tid];
        g_Psum[((size_t)bh*NSEG + seg)*Tt + tid] = s;
    }

    #pragma unroll
    for (int m = 0; m < 2; m++) {
        int r0 = m*16 + g, r1 = m*16 + g + 8;
        int d0 = w*8 + 2*t4;
        if (r0 < Tt)
            *(float2*)&g_Pacc[(((size_t)bh*NSEG + seg)*Tt + r0)*64 + d0] =
                make_float2(o[m][0], o[m][1]);
        if (r1 < Tt)
            *(float2*)&g_Pacc[(((size_t)bh*NSEG + seg)*Tt + r1)*64 + d0] =
                make_float2(o[m][2], o[m][3]);
    }
}

// ---------------- helper: block layernorm over 512 ----------------
__device__ void ln_row512(const float* in, float* out, const float* g, const float* bb,
                          float* red, int tid) {
    float v = in[tid];
    float s = v, sq = v*v;
    for (int o = 16; o; o >>= 1) {
        s  += __shfl_down_sync(0xffffffffu, s, o);
        sq += __shfl_down_sync(0xffffffffu, sq, o);
    }
    int wid = tid >> 5, lane = tid & 31;
    if (lane == 0) { red[wid] = s; red[16 + wid] = sq; }
    __syncthreads();
    if (tid == 0) {
        float S = 0.f, SQ = 0.f;
        for (int w = 0; w < 16; w++) { S += red[w]; SQ += red[16 + w]; }
        float m = S * (1.f/512.f);
        red[32] = m;
        red[33] = rsqrtf(SQ * (1.f/512.f) - m*m + EPSV);
    }
    __syncthreads();
    float m = red[32], rs = red[33];
    out[tid] = (v - m)*rs*g[tid] + bb[tid];
    __syncthreads();
}

// ---------------- K4: cls path, 1 row/block, 4-way ILP GEMVs ----------
__global__ __launch_bounds__(512) void k_cls(const float* __restrict__ x,
        const float* __restrict__ proj0_w, const float* __restrict__ proj0_b,
        const float* __restrict__ g2, const float* __restrict__ b2,
        const float* __restrict__ fc1_w, const float* __restrict__ fc1_b,
        const float* __restrict__ fc2_w, const float* __restrict__ fc2_b,
        const float* __restrict__ g3, const float* __restrict__ b3,
        const float* __restrict__ kv1_w, const float* __restrict__ q1_w) {
    __shared__ float cer[512];
    __shared__ float cls[512];
    __shared__ float yb[512];
    __shared__ float hb[2048];
    __shared__ float red[40];
    int tid = threadIdx.x;
    int r = blockIdx.x;
    int b = r / Tt, t = r % Tt;

    if (r == 0 && tid < Bq*Hh) g_cnt[tid] = 0;

    {
        int h = tid >> 6, d = tid & 63;
        int bh = b*8 + h;
        float accv = 0.f, s = 0.f;
        for (int sg = 0; sg < NSEG; sg++) {
            accv += g_Pacc[(((size_t)bh*NSEG + sg)*Tt + t)*64 + d];
            s    += g_Psum[((size_t)bh*NSEG + sg)*Tt + t];
        }
        cer[tid] = accv / s;
    }
    __syncthreads();
    // proj0 + residual (4 acc, unrolled)
    {
        float a0 = proj0_b[tid], a1 = 0.f, a2 = 0.f, a3 = 0.f;
        #pragma unroll 4
        for (int k = 0; k < 512; k += 4) {
            a0 = fmaf(cer[k],     proj0_w[(size_t)k*512 + tid],       a0);
            a1 = fmaf(cer[k + 1], proj0_w[(size_t)(k + 1)*512 + tid], a1);
            a2 = fmaf(cer[k + 2], proj0_w[(size_t)(k + 2)*512 + tid], a2);
            a3 = fmaf(cer[k + 3], proj0_w[(size_t)(k + 3)*512 + tid], a3);
        }
        cls[tid] = x[((size_t)b*Ntok + t)*512 + tid] + ((a0 + a1) + (a2 + a3));
    }
    __syncthreads();
    ln_row512(cls, yb, g2, b2, red, tid);
    // fc1 + exact gelu (4 acc each j, unrolled)
    #pragma unroll
    for (int jj = 0; jj < 4; jj++) {
        int j = tid + jj*512;
        float a0 = fc1_b[j], a1 = 0.f, a2 = 0.f, a3 = 0.f;
        #pragma unroll 4
        for (int k = 0; k < 512; k += 4) {
            a0 = fmaf(yb[k],     fc1_w[(size_t)k*2048 + j],       a0);
            a1 = fmaf(yb[k + 1], fc1_w[(size_t)(k + 1)*2048 + j], a1);
            a2 = fmaf(yb[k + 2], fc1_w[(size_t)(k + 2)*2048 + j], a2);
            a3 = fmaf(yb[k + 3], fc1_w[(size_t)(k + 3)*2048 + j], a3);
        }
        float a = (a0 + a1) + (a2 + a3);
        hb[j] = 0.5f*a*(1.0f + erff(a*0.70710678118654752f));
    }
    __syncthreads();
    // fc2 + residual (4 acc, unrolled)
    {
        float a0 = fc2_b[tid], a1 = 0.f, a2 = 0.f, a3 = 0.f;
        #pragma unroll 4
        for (int k = 0; k < 2048; k += 4) {
            a0 = fmaf(hb[k],     fc2_w[(size_t)k*512 + tid],       a0);
            a1 = fmaf(hb[k + 1], fc2_w[(size_t)(k + 1)*512 + tid], a1);
            a2 = fmaf(hb[k + 2], fc2_w[(size_t)(k + 2)*512 + tid], a2);
            a3 = fmaf(hb[k + 3], fc2_w[(size_t)(k + 3)*512 + tid], a3);
        }
        cls[tid] += (a0 + a1) + (a2 + a3);
    }
    __syncthreads();
    ln_row512(cls, yb, g3, b3, red, tid);
    // k1 overwrite + q1 (2x2 acc, unrolled)
    {
        float ak0 = 0.f, ak1 = 0.f, aq0 = 0.f, aq1 = 0.f;
        #pragma unroll 4
        for (int k = 0; k < 512; k += 2) {
            float y0 = yb[k], y1 = yb[k + 1];
            ak0 = fmaf(y0, kv1_w[(size_t)k*1024 + tid],       ak0);
            ak1 = fmaf(y1, kv1_w[(size_t)(k + 1)*1024 + tid], ak1);
            aq0 = fmaf(y0, q1_w[(size_t)k*512 + tid],         aq0);
            aq1 = fmaf(y1, q1_w[(size_t)(k + 1)*512 + tid],   aq1);
        }
        int h = tid >> 6, d = tid & 63;
        g_K1[(((size_t)b*Hh + h)*Ntok + t)*64 + d] = ak0 + ak1;
        g_q1[(size_t)r*512 + tid] = aq0 + aq1;
    }
}

// ---------------- K5: exp(logits) via mma + in-kernel finalize of softmax ----
__global__ __launch_bounds__(256) void k_logits_mma(float* __restrict__ out) {
    __shared__ float Qs[32*PSTR];
    __shared__ float Ks[2*64*PSTR];
    __shared__ float ws[8*32];
    __shared__ int slast;
    __shared__ float tinv[Tt];

    int bh = blockIdx.x, seg = blockIdx.y;
    int b = bh >> 3, h = bh & 7;
    int tid = threadIdx.x;
    int lane = tid & 31, w = tid >> 5;
    int g = lane >> 2, t4 = lane & 3;

    for (int i = tid; i < 32*64; i += 256) {
        int t = i >> 6, d = i & 63;
        float v = (t < Tt) ? SCALEV * g_q1[(size_t)b*Tt*512 + h*(Tt*Dd) + t*Dd + d] : 0.f;
        Qs[t*PSTR + d] = __uint_as_float(tf32r(v));
    }

    const float* Kb = g_K1 + (size_t)bh*Ntok*64;
    uint32_t KsU = smem_u32(Ks);
    float ssum[4] = {0.f, 0.f, 0.f, 0.f};

    auto loadK = [&](int ch, int buf) {
        int nc = seg*256 + ch*64;
        uint32_t kb = KsU + (uint32_t)buf*64*PSTR*4;
        #pragma unroll
        for (int it = 0; it < 2; it++) {
            int slot = tid + it*256;
            int r = slot >> 3, c8 = (slot & 7)*8;
            int gn = nc + r;
            bool p = gn < Ntok;
            int gc = p ? gn : 0;
            int sz = p ? 16 : 0;
            cp_async16z(kb + (r*PSTR + c8)*4,      Kb + (size_t)gc*64 + c8,     sz);
            cp_async16z(kb + (r*PSTR + c8 + 4)*4,  Kb + (size_t)gc*64 + c8 + 4, sz);
        }
        CP_COMMIT();
    };

    loadK(0, 0);
    for (int ch = 0; ch < 4; ch++) {
        if (ch < 3) loadK(ch + 1, (ch + 1) & 1);
        if (ch < 3) { CP_WAIT1(); } else { CP_WAIT0(); }
        __syncthreads();

        int buf = ch & 1;
        const float* K = Ks + buf*64*PSTR;
        int nc = seg*256 + ch*64;

        float s[2][4];
        #pragma unroll
        for (int m = 0; m < 2; m++)
            #pragma unroll
            for (int e = 0; e < 4; e++) s[m][e] = 0.f;
        #pragma unroll
        for (int ks = 0; ks < 8; ks++) {
            uint32_t bfr[2];
            bfr[0] = __float_as_uint(K[(w*8 + g)*PSTR + ks*8 + t4]);
            bfr[1] = __float_as_uint(K[(w*8 + g)*PSTR + ks*8 + t4 + 4]);
            #pragma unroll
            for (int m = 0; m < 2; m++) {
                uint32_t afr[4];
                int ab = (m*16 + g)*PSTR + ks*8 + t4;
                afr[0] = __float_as_uint(Qs[ab]);
                afr[1] = __float_as_uint(Qs[ab + 8*PSTR]);
                afr[2] = __float_as_uint(Qs[ab + 4]);
                afr[3] = __float_as_uint(Qs[ab + 8*PSTR + 4]);
                mma1688(s[m], afr, bfr);
            }
        }

        int tok0 = nc + w*8 + 2*t4;
        int tok1 = tok0 + 1;
        #pragma unroll
        for (int m = 0; m < 2; m++) {
            float e0 = __expf(s[m][0]), e1 = __expf(s[m][1]);
            float e2 = __expf(s[m][2]), e3 = __expf(s[m][3]);
            if (tok0 >= Ntok) { e0 = 0.f; e2 = 0.f; }
            if (tok1 >= Ntok) { e1 = 0.f; e3 = 0.f; }
            int r0 = m*16 + g, r1 = m*16 + g + 8;
            if (r0 < Tt) {
                size_t ob = ((size_t)bh*Tt + r0)*Ntok;
                if (tok0 < Ntok) out[ob + tok0] = e0;
                if (tok1 < Ntok) out[ob + tok1] = e1;
            }
            if (r1 < Tt) {
                size_t ob = ((size_t)bh*Tt + r1)*Ntok;
                if (tok0 < Ntok) out[ob + tok0] = e2;
                if (tok1 < Ntok) out[ob + tok1] = e3;
            }
            float r0s = e0 + e1, r1s = e2 + e3;
            r0s += __shfl_xor_sync(0xffffffffu, r0s, 1);
            r0s += __shfl_xor_sync(0xffffffffu, r0s, 2);
            r1s += __shfl_xor_sync(0xffffffffu, r1s, 1);
            r1s += __shfl_xor_sync(0xffffffffu, r1s, 2);
            if (t4 == 0) { ssum[m*2] += r0s; ssum[m*2 + 1] += r1s; }
        }
        __syncthreads();
    }

    if (t4 == 0) {
        ws[w*32 + g]      = ssum[0];
        ws[w*32 + g + 8]  = ssum[1];
        ws[w*32 + 16 + g] = ssum[2];
        ws[w*32 + 24 + g] = ssum[3];
    }
    __syncthreads();
    if (tid < Tt) {
        float s = 0.f;
        #pragma unroll
        for (int wq = 0; wq < 8; wq++) s += ws[wq*32 + tid];
        g_Fsum[((size_t)bh*NSEG + seg)*Tt + tid] = s;
    }

    __threadfence();
    __syncthreads();
    if (tid == 0) slast = atomicAdd(&g_cnt[bh], 1);
    __syncthreads();
    if (slast == NSEG - 1) {
        __threadfence();
        if (tid < Tt) {
            float S = 0.f;
            for (int sg = 0; sg < NSEG; sg++)
                S += g_Fsum[((size_t)bh*NSEG + sg)*Tt + tid];
            tinv[tid] = 1.f / S;
        }
        __syncthreads();
        size_t base = (size_t)bh*Tt*Ntok;
        for (int t = 0; t < Tt; t++) {
            float ti = tinv[t];
            size_t rb = base + (size_t)t*Ntok;
            for (int n = tid; n < Ntok; n += 256)
                out[rb + n] *= ti;
        }
    }
}

// ---------------- launch ----------------
extern "C" void kernel_launch(void* const* d_in, const int* in_sizes, int n_in,
                              void* d_out, int out_size) {
    const float* x       = (const float*)d_in[0];
    const float* ln1_g   = (const float*)d_in[1];
    const float* ln1_b   = (const float*)d_in[2];
    const float* kv0_w   = (const float*)d_in[3];
    const float* q0_w    = (const float*)d_in[4];
    const float* proj0_w = (const float*)d_in[5];
    const float* proj0_b = (const float*)d_in[6];
    const float* ln2_g   = (const float*)d_in[7];
    const float* ln2_b   = (const float*)d_in[8];
    const float* fc1_w   = (const float*)d_in[9];
    const float* fc1_b   = (const float*)d_in[10];
    const float* fc2_w   = (const float*)d_in[11];
    const float* fc2_b   = (const float*)d_in[12];
    const float* ln3_g   = (const float*)d_in[13];
    const float* ln3_b   = (const float*)d_in[14];
    const float* kv1_w   = (const float*)d_in[15];
    const float* q1_w    = (const float*)d_in[16];
    float* out = (float*)d_out;

    cudaFuncSetAttribute(k_gemm_mma, cudaFuncAttributeMaxDynamicSharedMemorySize, GEMM_SMEM);
    cudaFuncSetAttribute(k_attn0_mma, cudaFuncAttributeMaxDynamicSharedMemorySize, ATT_SMEM);

    k_prepstats<<<1536 + MTILES + Bq*Tt, 256>>>(x, kv0_w, kv1_w, q0_w,
                                                ln1_g, ln1_b, ln3_g, ln3_b);
    k_gemm_mma<<<dim3(12, MTILES), 256, GEMM_SMEM>>>();
    k_attn0_mma<<<dim3(Bq*Hh, NSEG), 256, ATT_SMEM>>>();
    k_cls<<<Bq*Tt, 512>>>(x, proj0_w, proj0_b, ln2_g, ln2_b,
                          fc1_w, fc1_b, fc2_w, fc2_b, ln3_g, ln3_b, kv1_w, q1_w);
    k_logits_mma<<<dim3(Bq*Hh, NSEG), 256>>>(out);
}

// round 16
// speedup vs baseline: 1.1613x; 1.1613x over previous
#include <cuda_runtime.h>
#include <cstdint>
#include <math.h>

#define Bq 8
#define Ntok 9237
#define Cc 512
#define Tt 21
#define Hh 8
#define Dd 64
#define HIDN 2048
#define M_ROWS (Bq*Ntok)          // 73896
#define EPSV 1e-5f
#define SCALEV 0.125f
#define NSEG 37                    // ceil(9237/256)
#define PSTR 72                    // smem row stride (floats): conflict-free frags
#define MTILES 578                 // ceil(73896/128)

// ---------------- static scratch (no allocations allowed) ----------------
__device__ __align__(16) float g_mean[M_ROWS];
__device__ __align__(16) float g_rstd[M_ROWS];
__device__ __align__(16) uint32_t g_Afrag[(size_t)MTILES*16*4096];  // LN'd A, tf32, fragment order
__device__ __align__(16) float g_Bfrag[1536*512];   // fragment-packed, gamma-folded, tf32
__device__ __align__(16) float g_biasc[1536];
__device__ __align__(16) float g_K0[(size_t)Bq*Hh*Ntok*Dd];
__device__ __align__(16) float g_V0[(size_t)Bq*Hh*Ntok*Dd];
__device__ __align__(16) float g_K1[(size_t)Bq*Hh*Ntok*Dd];
__device__ __align__(16) float g_q0[Bq*Tt*Cc];
__device__ __align__(16) float g_q1[Bq*Tt*Cc];
__device__ __align__(16) float g_Pacc[(size_t)Bq*Hh*NSEG*Tt*Dd];
__device__ __align__(16) float g_Psum[Bq*Hh*NSEG*Tt];
__device__ __align__(16) float g_Fsum[Bq*Hh*NSEG*Tt];
__device__ int g_cnt[Bq*Hh];

// ---------------- helpers ----------------
__device__ __forceinline__ uint32_t smem_u32(const void* p) {
    uint32_t a;
    asm("{ .reg .u64 t; cvta.to.shared.u64 t, %1; cvt.u32.u64 %0, t; }" : "=r"(a) : "l"(p));
    return a;
}
__device__ __forceinline__ uint32_t tf32r(float f) {
    uint32_t u; asm("cvt.rna.tf32.f32 %0, %1;" : "=r"(u) : "f"(f)); return u;
}
__device__ __forceinline__ void cp_async16(uint32_t smem, const void* g) {
    asm volatile("cp.async.cg.shared.global [%0], [%1], 16;" :: "r"(smem), "l"(g));
}
__device__ __forceinline__ void cp_async16z(uint32_t smem, const void* g, int szbytes) {
    asm volatile("cp.async.cg.shared.global [%0], [%1], 16, %2;"
                 :: "r"(smem), "l"(g), "r"(szbytes));
}
#define CP_COMMIT() asm volatile("cp.async.commit_group;" ::: "memory")
#define CP_WAIT0()  asm volatile("cp.async.wait_group 0;" ::: "memory")
#define CP_WAIT1()  asm volatile("cp.async.wait_group 1;" ::: "memory")

__device__ __forceinline__ void mma1688(float* c, const uint32_t* a, const uint32_t* b) {
    asm volatile(
        "mma.sync.aligned.m16n8k8.row.col.f32.tf32.tf32.f32 "
        "{%0,%1,%2,%3}, {%4,%5,%6,%7}, {%8,%9}, {%0,%1,%2,%3};"
        : "+f"(c[0]), "+f"(c[1]), "+f"(c[2]), "+f"(c[3])
        : "r"(a[0]), "r"(a[1]), "r"(a[2]), "r"(a[3]), "r"(b[0]), "r"(b[1]));
}

// ---------------- K1: prep (B frags) + LN stats + A frags + q0, one launch ----
__global__ __launch_bounds__(256) void k_prepstats(
        const float* __restrict__ x,
        const float* __restrict__ kv0_w, const float* __restrict__ kv1_w,
        const float* __restrict__ q0_w,
        const float* __restrict__ g1, const float* __restrict__ b1,
        const float* __restrict__ g3, const float* __restrict__ b3) {
    __shared__ float shbuf[128*33 + 256];
    int bid = blockIdx.x;
    int tid = threadIdx.x;
    if (bid < 1536) {
        int n = bid;
        const float *W, *g, *b; int col;
        if (n < 1024) { W = kv0_w; g = g1; b = b1; col = n; }
        else          { W = kv1_w; g = g3; b = b3; col = n - 1024; }
        int bx = n >> 7;
        int np = n & 127;
        int n8 = np >> 3, gg = np & 7;
        float partial = 0.f;
        for (int k = tid; k < 512; k += 256) {
            float w = W[(size_t)k*1024 + col] * g[k];
            int c  = k >> 5;
            int kc = k & 31;
            int ks = kc >> 3, kin = kc & 7;
            int t = kin & 3, reg = kin >> 2;
            int lane = gg*4 + t;
            size_t idx = (size_t)(bx*16 + c)*4096 + ((n8*4 + ks)*32 + lane)*2 + reg;
            g_Bfrag[idx] = __uint_as_float(tf32r(w));
            partial += b[k] * w;
        }
        float* red = shbuf;
        red[tid] = partial; __syncthreads();
        for (int s = 128; s; s >>= 1) {
            if (tid < s) red[tid] += red[tid + s];
            __syncthreads();
        }
        if (tid == 0) g_biasc[n] = red[0];
    } else if (bid < 1536 + MTILES) {
        float* ms = shbuf;
        float* rs = shbuf + 128;
        float* xs = shbuf + 256;
        int rowBase = (bid - 1536)*128;
        {
            int rl = tid >> 1;
            int row = rowBase + rl;
            int half = tid & 1;
            float s = 0.f, sq = 0.f;
            if (row < M_ROWS) {
                const float4* xr = (const float4*)(x + (size_t)row*512 + half*256);
                #pragma unroll 8
                for (int i = 0; i < 64; i++) {
                    float4 v = xr[i];
                    s  += v.x + v.y + v.z + v.w;
                    sq += v.x*v.x + v.y*v.y + v.z*v.z + v.w*v.w;
                }
            }
            s  += __shfl_xor_sync(0xffffffffu, s, 1);
            sq += __shfl_xor_sync(0xffffffffu, sq, 1);
            if (half == 0) {
                float m = s * (1.f/512.f);
                float var = sq * (1.f/512.f) - m*m;
                float rr = rsqrtf(var + EPSV);
                ms[rl] = m; rs[rl] = rr;
                if (row < M_ROWS) { g_mean[row] = m; g_rstd[row] = rr; }
            }
        }
        __syncthreads();
        uint32_t* dst = g_Afrag + (size_t)(bid - 1536)*16*4096;
        for (int c = 0; c < 16; c++) {
            #pragma unroll
            for (int it = 0; it < 4; it++) {
                int slot = tid + it*256;
                int row = slot >> 3, q = slot & 7;
                int r = rowBase + row;
                float4 v = (r < M_ROWS)
                    ? *(const float4*)(x + (size_t)r*512 + c*32 + q*4)
                    : make_float4(0,0,0,0);
                float* xp = &xs[row*33 + q*4];
                xp[0] = v.x; xp[1] = v.y; xp[2] = v.z; xp[3] = v.w;
            }
            __syncthreads();
            #pragma unroll
            for (int it = 0; it < 16; it++) {
                int f = tid + it*256;
                int reg = f & 3, lane = (f >> 2) & 31, ks = (f >> 7) & 3, mtile = f >> 9;
                int g = lane >> 2, t4 = lane & 3;
                int rl = mtile*16 + (reg & 1)*8 + g;
                int kl = ks*8 + t4 + (reg >> 1)*4;
                float v = (xs[rl*33 + kl] - ms[rl]) * rs[rl];
                dst[c*4096 + f] = tf32r(v);
            }
            __syncthreads();
        }
    } else {
        int r = bid - 1536 - MTILES;
        int b = r / Tt, t = r % Tt;
        int row = b*Ntok + t;
        float* y = shbuf;
        float* red2 = shbuf + 512;
        float v0 = x[(size_t)row*512 + tid];
        float v1 = x[(size_t)row*512 + tid + 256];
        float s = v0 + v1, sq = v0*v0 + v1*v1;
        for (int o = 16; o; o >>= 1) {
            s  += __shfl_down_sync(0xffffffffu, s, o);
            sq += __shfl_down_sync(0xffffffffu, sq, o);
        }
        int wid = tid >> 5, lane = tid & 31;
        if (lane == 0) { red2[wid] = s; red2[32 + wid] = sq; }
        __syncthreads();
        if (tid == 0) {
            float S = 0.f, SQ = 0.f;
            for (int w = 0; w < 8; w++) { S += red2[w]; SQ += red2[32 + w]; }
            float m = S * (1.f/512.f);
            red2[16] = m;
            red2[17] = rsqrtf(SQ * (1.f/512.f) - m*m + EPSV);
        }
        __syncthreads();
        float m = red2[16], rr = red2[17];
        float y0 = (v0 - m)*rr*g1[tid]       + b1[tid];
        float y1 = (v1 - m)*rr*g1[tid + 256] + b1[tid + 256];
        __syncthreads();
        y[tid] = y0;
        y[tid + 256] = y1;
        __syncthreads();
        // q0: float4-column GEMV — thread owns 4 cols via two halves (512 cols)
        #pragma unroll
        for (int cc = 0; cc < 2; cc++) {
            int cg = tid + cc*256;       // 0..511 col-group? cols are 512 -> 128 groups...
            if (cg < 128) {
                float a0 = 0.f, a1 = 0.f, a2 = 0.f, a3 = 0.f;
                for (int k = 0; k < 512; k++) {
                    float yv = y[k];
                    float4 wv = *(const float4*)(q0_w + (size_t)k*512 + cg*4);
                    a0 = fmaf(yv, wv.x, a0); a1 = fmaf(yv, wv.y, a1);
                    a2 = fmaf(yv, wv.z, a2); a3 = fmaf(yv, wv.w, a3);
                }
                float4 o = make_float4(a0, a1, a2, a3);
                *(float4*)(g_q0 + (size_t)r*512 + cg*4) = o;
            }
        }
    }
}

// ---------------- K2: pure-stream tf32 mma GEMM (3-stage cp.async) ----------------
#define GEMM_SMEM (3*32768)

__global__ __launch_bounds__(256, 2) void k_gemm_mma() {
    extern __shared__ uint32_t dsmu[];

    const int tid = threadIdx.x;
    const int bx = blockIdx.x;
    const int by = blockIdx.y;
    const int colBase = bx * 128;
    const int rowBase = by * 128;

    const int lane = tid & 31, wid = tid >> 5;
    const int warp_m = wid & 1, warp_n = wid >> 1;
    const int g = lane >> 2, t4 = lane & 3;

    const uint32_t sbase = smem_u32(dsmu);
    const uint32_t* Asrc = g_Afrag + (size_t)by*16*4096;
    const uint32_t* Bsrc = (const uint32_t*)g_Bfrag + (size_t)bx*16*4096;

    auto issue = [&](int c, int s) {
        uint32_t dstA = sbase + (uint32_t)s*32768;
        const uint32_t* a = Asrc + c*4096;
        const uint32_t* b = Bsrc + c*4096;
        #pragma unroll
        for (int it = 0; it < 4; it++) {
            int off = (tid + it*256)*4;
            cp_async16(dstA + off*4, a + off);
            cp_async16(dstA + 16384 + off*4, b + off);
        }
        CP_COMMIT();
    };

    float acc[4][4][4];
    #pragma unroll
    for (int i = 0; i < 4; i++)
        #pragma unroll
        for (int j = 0; j < 4; j++)
            #pragma unroll
            for (int k = 0; k < 4; k++) acc[i][j][k] = 0.f;

    issue(0, 0); issue(1, 1);

    int s = 0;
    for (int c = 0; c < 16; c++) {
        CP_WAIT1();
        __syncthreads();
        if (c + 2 < 16) issue(c + 2, (c + 2) % 3);
        else CP_COMMIT();

        const uint32_t* Af = dsmu + s*8192;
        const uint32_t* Bf = dsmu + s*8192 + 4096;
        #pragma unroll
        for (int ks = 0; ks < 4; ks++) {
            uint32_t bfr[4][2];
            #pragma unroll
            for (int nf = 0; nf < 4; nf++) {
                int fi = (((warp_n*4 + nf)*4 + ks)*32 + lane)*2;
                uint2 bv = *(const uint2*)(Bf + fi);
                bfr[nf][0] = bv.x;
                bfr[nf][1] = bv.y;
            }
            #pragma unroll
            for (int mf = 0; mf < 4; mf++) {
                int ai = (((warp_m*4 + mf)*4 + ks)*32 + lane)*4;
                uint4 av = *(const uint4*)(Af + ai);
                uint32_t afr[4] = {av.x, av.y, av.z, av.w};
                #pragma unroll
                for (int nf = 0; nf < 4; nf++)
                    mma1688(acc[mf][nf], afr, bfr[nf]);
            }
        }
        s = (s == 2) ? 0 : s + 1;
    }

    const int region = bx >> 2;
    float* dstB = (region == 0) ? g_K0 : (region == 1) ? g_V0 : g_K1;
    float2 bias[4];
    #pragma unroll
    for (int nf = 0; nf < 4; nf++) {
        int j = colBase + warp_n*32 + nf*8 + t4*2;
        bias[nf] = *(const float2*)(g_biasc + j);
    }
    #pragma unroll
    for (int mf = 0; mf < 4; mf++) {
        #pragma unroll
        for (int hi = 0; hi < 2; hi++) {
            int r = rowBase + warp_m*64 + mf*16 + g + hi*8;
            if (r >= M_ROWS) continue;
            int bb = r / Ntok, nt = r % Ntok;
            #pragma unroll
            for (int nf = 0; nf < 4; nf++) {
                int j = colBase + warp_n*32 + nf*8 + t4*2;
                int h = (j >> 6) & 7, d = j & 63;
                float2 v;
                v.x = acc[mf][nf][hi*2 + 0] + bias[nf].x;
                v.y = acc[mf][nf][hi*2 + 1] + bias[nf].y;
                *(float2*)(dstB + (((size_t)bb*Hh + h)*Ntok + nt)*64 + d) = v;
            }
        }
    }
}

// ---------------- K3: attn0 via mma, double-buffered K/V chunk pipeline ----------
#define ATT_SMEM ((32*PSTR + 2*64*PSTR + 2*64*PSTR + 32*PSTR)*4 + 8*32*4)

__global__ __launch_bounds__(256) void k_attn0_mma() {
    extern __shared__ float sm[];
    float* Qs = sm;
    float* Ks = Qs + 32*PSTR;
    float* Vs = Ks + 2*64*PSTR;
    float* Ps = Vs + 2*64*PSTR;
    float* ws = Ps + 32*PSTR;

    int bh = blockIdx.x, seg = blockIdx.y;
    int b = bh >> 3, h = bh & 7;
    int tid = threadIdx.x;
    int lane = tid & 31, w = tid >> 5;
    int g = lane >> 2, t4 = lane & 3;

    for (int i = tid; i < 32*64; i += 256) {
        int t = i >> 6, d = i & 63;
        float v = (t < Tt) ? SCALEV * g_q0[(size_t)b*Tt*512 + h*(Tt*Dd) + t*Dd + d] : 0.f;
        Qs[t*PSTR + d] = __uint_as_float(tf32r(v));
    }

    const float* Kb = g_K0 + (size_t)bh*Ntok*64;
    const float* Vb = g_V0 + (size_t)bh*Ntok*64;
    uint32_t KsU = smem_u32(Ks), VsU = smem_u32(Vs);

    auto loadKV = [&](int ch, int buf) {
        int nc = seg*256 + ch*64;
        uint32_t kb = KsU + (uint32_t)buf*64*PSTR*4;
        uint32_t vb = VsU + (uint32_t)buf*64*PSTR*4;
        #pragma unroll
        for (int it = 0; it < 4; it++) {
            int slot = tid + it*256;
            int r = slot >> 4, c4 = (slot & 15)*4;
            int gn = nc + r;
            bool p = gn < Ntok;
            int gc = p ? gn : 0;
            int sz = p ? 16 : 0;
            cp_async16z(kb + (r*PSTR + c4)*4, Kb + (size_t)gc*64 + c4, sz);
            cp_async16z(vb + (r*PSTR + c4)*4, Vb + (size_t)gc*64 + c4, sz);
        }
        CP_COMMIT();
    };

    float o[2][4];
    #pragma unroll
    for (int m = 0; m < 2; m++)
        #pragma unroll
        for (int e = 0; e < 4; e++) o[m][e] = 0.f;
    float ssum[4] = {0.f, 0.f, 0.f, 0.f};

    loadKV(0, 0);
    for (int ch = 0; ch < 4; ch++) {
        if (ch < 3) loadKV(ch + 1, (ch + 1) & 1);
        if (ch < 3) { CP_WAIT1(); } else { CP_WAIT0(); }
        __syncthreads();

        int buf = ch & 1;
        const float* K = Ks + buf*64*PSTR;
        const float* V = Vs + buf*64*PSTR;
        int nc = seg*256 + ch*64;

        float s[2][4];
        #pragma unroll
        for (int m = 0; m < 2; m++)
            #pragma unroll
            for (int e = 0; e < 4; e++) s[m][e] = 0.f;
        #pragma unroll
        for (int ks = 0; ks < 8; ks++) {
            uint32_t bfr[2];
            bfr[0] = __float_as_uint(K[(w*8 + g)*PSTR + ks*8 + t4]);
            bfr[1] = __float_as_uint(K[(w*8 + g)*PSTR + ks*8 + t4 + 4]);
            #pragma unroll
            for (int m = 0; m < 2; m++) {
                uint32_t afr[4];
                int ab = (m*16 + g)*PSTR + ks*8 + t4;
                afr[0] = __float_as_uint(Qs[ab]);
                afr[1] = __float_as_uint(Qs[ab + 8*PSTR]);
                afr[2] = __float_as_uint(Qs[ab + 4]);
                afr[3] = __float_as_uint(Qs[ab + 8*PSTR + 4]);
                mma1688(s[m], afr, bfr);
            }
        }

        int tok0 = nc + w*8 + 2*t4;
        int tok1 = tok0 + 1;
        #pragma unroll
        for (int m = 0; m < 2; m++) {
            float e0 = __expf(s[m][0]), e1 = __expf(s[m][1]);
            float e2 = __expf(s[m][2]), e3 = __expf(s[m][3]);
            if (tok0 >= Ntok) { e0 = 0.f; e2 = 0.f; }
            if (tok1 >= Ntok) { e1 = 0.f; e3 = 0.f; }
            e0 = __uint_as_float(tf32r(e0)); e1 = __uint_as_float(tf32r(e1));
            e2 = __uint_as_float(tf32r(e2)); e3 = __uint_as_float(tf32r(e3));
            *(float2*)&Ps[(m*16 + g)*PSTR + w*8 + 2*t4]     = make_float2(e0, e1);
            *(float2*)&Ps[(m*16 + g + 8)*PSTR + w*8 + 2*t4] = make_float2(e2, e3);
            float r0 = e0 + e1, r1 = e2 + e3;
            r0 += __shfl_xor_sync(0xffffffffu, r0, 1);
            r0 += __shfl_xor_sync(0xffffffffu, r0, 2);
            r1 += __shfl_xor_sync(0xffffffffu, r1, 1);
            r1 += __shfl_xor_sync(0xffffffffu, r1, 2);
            if (t4 == 0) { ssum[m*2] += r0; ssum[m*2 + 1] += r1; }
        }
        __syncthreads();

        #pragma unroll
        for (int ks = 0; ks < 8; ks++) {
            uint32_t bfr[2];
            bfr[0] = __float_as_uint(V[(ks*8 + t4)*PSTR + w*8 + g]);
            bfr[1] = __float_as_uint(V[(ks*8 + t4 + 4)*PSTR + w*8 + g]);
            #pragma unroll
            for (int m = 0; m < 2; m++) {
                uint32_t afr[4];
                int ab = (m*16 + g)*PSTR + ks*8 + t4;
                afr[0] = __float_as_uint(Ps[ab]);
                afr[1] = __float_as_uint(Ps[ab + 8*PSTR]);
                afr[2] = __float_as_uint(Ps[ab + 4]);
                afr[3] = __float_as_uint(Ps[ab + 8*PSTR + 4]);
                mma1688(o[m], afr, bfr);
            }
        }
        __syncthreads();
    }

    if (t4 == 0) {
        ws[w*32 + g]      = ssum[0];
        ws[w*32 + g + 8]  = ssum[1];
        ws[w*32 + 16 + g] = ssum[2];
        ws[w*32 + 24 + g] = ssum[3];
    }
    __syncthreads();
    if (tid < Tt) {
        float s = 0.f;
        #pragma unroll
        for (int wq = 0; wq < 8; wq++) s += ws[wq*32 + tid];
        g_Psum[((size_t)bh*NSEG + seg)*Tt + tid] = s;
    }

    #pragma unroll
    for (int m = 0; m < 2; m++) {
        int r0 = m*16 + g, r1 = m*16 + g + 8;
        int d0 = w*8 + 2*t4;
        if (r0 < Tt)
            *(float2*)&g_Pacc[(((size_t)bh*NSEG + seg)*Tt + r0)*64 + d0] =
                make_float2(o[m][0], o[m][1]);
        if (r1 < Tt)
            *(float2*)&g_Pacc[(((size_t)bh*NSEG + seg)*Tt + r1)*64 + d0] =
                make_float2(o[m][2], o[m][3]);
    }
}

// ---------------- helper: block layernorm over 512 ----------------
__device__ void ln_row512(const float* in, float* out, const float* g, const float* bb,
                          float* red, int tid) {
    float v = in[tid];
    float s = v, sq = v*v;
    for (int o = 16; o; o >>= 1) {
        s  += __shfl_down_sync(0xffffffffu, s, o);
        sq += __shfl_down_sync(0xffffffffu, sq, o);
    }
    int wid = tid >> 5, lane = tid & 31;
    if (lane == 0) { red[wid] = s; red[16 + wid] = sq; }
    __syncthreads();
    if (tid == 0) {
        float S = 0.f, SQ = 0.f;
        for (int w = 0; w < 16; w++) { S += red[w]; SQ += red[16 + w]; }
        float m = S * (1.f/512.f);
        red[32] = m;
        red[33] = rsqrtf(SQ * (1.f/512.f) - m*m + EPSV);
    }
    __syncthreads();
    float m = red[32], rs = red[33];
    out[tid] = (v - m)*rs*g[tid] + bb[tid];
    __syncthreads();
}

// ---------------- K4: cls path, float4-column GEMVs with k-split + smem reduce ----
__global__ __launch_bounds__(512) void k_cls(const float* __restrict__ x,
        const float* __restrict__ proj0_w, const float* __restrict__ proj0_b,
        const float* __restrict__ g2, const float* __restrict__ b2,
        const float* __restrict__ fc1_w, const float* __restrict__ fc1_b,
        const float* __restrict__ fc2_w, const float* __restrict__ fc2_b,
        const float* __restrict__ g3, const float* __restrict__ b3,
        const float* __restrict__ kv1_w, const float* __restrict__ q1_w) {
    __shared__ float cer[512];
    __shared__ float cls[512];
    __shared__ float yb[512];
    __shared__ float hb[2048];
    __shared__ float part[2048];
    __shared__ float red[40];
    int tid = threadIdx.x;
    int r = blockIdx.x;
    int b = r / Tt, t = r % Tt;

    if (r == 0 && tid < Bq*Hh) g_cnt[tid] = 0;

    // ce inline
    {
        int h = tid >> 6, d = tid & 63;
        int bh = b*8 + h;
        float accv = 0.f, s = 0.f;
        for (int sg = 0; sg < NSEG; sg++) {
            accv += g_Pacc[(((size_t)bh*NSEG + sg)*Tt + t)*64 + d];
            s    += g_Psum[((size_t)bh*NSEG + sg)*Tt + t];
        }
        cer[tid] = accv / s;
    }
    __syncthreads();
    // proj0: 4x k-split, float4 cols
    {
        int kq = tid >> 7, cg = tid & 127;
        float a0 = 0.f, a1 = 0.f, a2 = 0.f, a3 = 0.f;
        int k0 = kq*128;
        for (int k = k0; k < k0 + 128; k++) {
            float yv = cer[k];
            float4 wv = *(const float4*)(proj0_w + (size_t)k*512 + cg*4);
            a0 = fmaf(yv, wv.x, a0); a1 = fmaf(yv, wv.y, a1);
            a2 = fmaf(yv, wv.z, a2); a3 = fmaf(yv, wv.w, a3);
        }
        part[kq*512 + cg*4 + 0] = a0;
        part[kq*512 + cg*4 + 1] = a1;
        part[kq*512 + cg*4 + 2] = a2;
        part[kq*512 + cg*4 + 3] = a3;
    }
    __syncthreads();
    {
        float s = part[tid] + part[512 + tid] + part[1024 + tid] + part[1536 + tid];
        cls[tid] = x[((size_t)b*Ntok + t)*512 + tid] + s + proj0_b[tid];
    }
    __syncthreads();
    ln_row512(cls, yb, g2, b2, red, tid);
    // fc1: thread owns 4 cols (tid*4..), full k
    {
        float a0 = fc1_b[tid*4], a1 = fc1_b[tid*4 + 1];
        float a2 = fc1_b[tid*4 + 2], a3 = fc1_b[tid*4 + 3];
        for (int k = 0; k < 512; k++) {
            float yv = yb[k];
            float4 wv = *(const float4*)(fc1_w + (size_t)k*2048 + tid*4);
            a0 = fmaf(yv, wv.x, a0); a1 = fmaf(yv, wv.y, a1);
            a2 = fmaf(yv, wv.z, a2); a3 = fmaf(yv, wv.w, a3);
        }
        hb[tid*4 + 0] = 0.5f*a0*(1.0f + erff(a0*0.70710678118654752f));
        hb[tid*4 + 1] = 0.5f*a1*(1.0f + erff(a1*0.70710678118654752f));
        hb[tid*4 + 2] = 0.5f*a2*(1.0f + erff(a2*0.70710678118654752f));
        hb[tid*4 + 3] = 0.5f*a3*(1.0f + erff(a3*0.70710678118654752f));
    }
    __syncthreads();
    // fc2: 4x k-split (512 each), float4 cols
    {
        int kq = tid >> 7, cg = tid & 127;
        float a0 = 0.f, a1 = 0.f, a2 = 0.f, a3 = 0.f;
        int k0 = kq*512;
        for (int k = k0; k < k0 + 512; k++) {
            float hv = hb[k];
            float4 wv = *(const float4*)(fc2_w + (size_t)k*512 + cg*4);
            a0 = fmaf(hv, wv.x, a0); a1 = fmaf(hv, wv.y, a1);
            a2 = fmaf(hv, wv.z, a2); a3 = fmaf(hv, wv.w, a3);
        }
        part[kq*512 + cg*4 + 0] = a0;
        part[kq*512 + cg*4 + 1] = a1;
        part[kq*512 + cg*4 + 2] = a2;
        part[kq*512 + cg*4 + 3] = a3;
    }
    __syncthreads();
    {
        float s = part[tid] + part[512 + tid] + part[1024 + tid] + part[1536 + tid];
        cls[tid] += s + fc2_b[tid];
    }
    __syncthreads();
    ln_row512(cls, yb, g3, b3, red, tid);
    // k1 + q1 fused: 2x k-split (256 each); cg<128 -> q1 cols, cg>=128 -> k1 cols
    {
        int kh = tid >> 8;            // 0..1
        int cg = tid & 255;           // 0..255
        const float* W;
        size_t stride;
        int col4;
        if (cg < 128) { W = q1_w;  stride = 512;  col4 = cg*4; }
        else          { W = kv1_w; stride = 1024; col4 = (cg - 128)*4; }
        float a0 = 0.f, a1 = 0.f, a2 = 0.f, a3 = 0.f;
        int k0 = kh*256;
        for (int k = k0; k < k0 + 256; k++) {
            float yv = yb[k];
            float4 wv = *(const float4*)(W + (size_t)k*stride + col4);
            a0 = fmaf(yv, wv.x, a0); a1 = fmaf(yv, wv.y, a1);
            a2 = fmaf(yv, wv.z, a2); a3 = fmaf(yv, wv.w, a3);
        }
        part[kh*1024 + cg*4 + 0] = a0;
        part[kh*1024 + cg*4 + 1] = a1;
        part[kh*1024 + cg*4 + 2] = a2;
        part[kh*1024 + cg*4 + 3] = a3;
    }
    __syncthreads();
    #pragma unroll
    for (int oo = 0; oo < 2; oo++) {
        int o = tid + oo*512;         // 0..1023
        float v = part[o] + part[1024 + o];
        if (o < 512) {
            g_q1[(size_t)r*512 + o] = v;
        } else {
            int col = o - 512;
            int h = col >> 6, d = col & 63;
            g_K1[(((size_t)b*Hh + h)*Ntok + t)*64 + d] = v;
        }
    }
}

// ---------------- K5: exp(logits) via mma + in-kernel finalize of softmax ----
__global__ __launch_bounds__(256) void k_logits_mma(float* __restrict__ out) {
    __shared__ float Qs[32*PSTR];
    __shared__ float Ks[2*64*PSTR];
    __shared__ float ws[8*32];
    __shared__ int slast;
    __shared__ float tinv[Tt];

    int bh = blockIdx.x, seg = blockIdx.y;
    int b = bh >> 3, h = bh & 7;
    int tid = threadIdx.x;
    int lane = tid & 31, w = tid >> 5;
    int g = lane >> 2, t4 = lane & 3;

    for (int i = tid; i < 32*64; i += 256) {
        int t = i >> 6, d = i & 63;
        float v = (t < Tt) ? SCALEV * g_q1[(size_t)b*Tt*512 + h*(Tt*Dd) + t*Dd + d] : 0.f;
        Qs[t*PSTR + d] = __uint_as_float(tf32r(v));
    }

    const float* Kb = g_K1 + (size_t)bh*Ntok*64;
    uint32_t KsU = smem_u32(Ks);
    float ssum[4] = {0.f, 0.f, 0.f, 0.f};

    auto loadK = [&](int ch, int buf) {
        int nc = seg*256 + ch*64;
        uint32_t kb = KsU + (uint32_t)buf*64*PSTR*4;
        #pragma unroll
        for (int it = 0; it < 2; it++) {
            int slot = tid + it*256;
            int r = slot >> 3, c8 = (slot & 7)*8;
            int gn = nc + r;
            bool p = gn < Ntok;
            int gc = p ? gn : 0;
            int sz = p ? 16 : 0;
            cp_async16z(kb + (r*PSTR + c8)*4,      Kb + (size_t)gc*64 + c8,     sz);
            cp_async16z(kb + (r*PSTR + c8 + 4)*4,  Kb + (size_t)gc*64 + c8 + 4, sz);
        }
        CP_COMMIT();
    };

    loadK(0, 0);
    for (int ch = 0; ch < 4; ch++) {
        if (ch < 3) loadK(ch + 1, (ch + 1) & 1);
        if (ch < 3) { CP_WAIT1(); } else { CP_WAIT0(); }
        __syncthreads();

        int buf = ch & 1;
        const float* K = Ks + buf*64*PSTR;
        int nc = seg*256 + ch*64;

        float s[2][4];
        #pragma unroll
        for (int m = 0; m < 2; m++)
            #pragma unroll
            for (int e = 0; e < 4; e++) s[m][e] = 0.f;
        #pragma unroll
        for (int ks = 0; ks < 8; ks++) {
            uint32_t bfr[2];
            bfr[0] = __float_as_uint(K[(w*8 + g)*PSTR + ks*8 + t4]);
            bfr[1] = __float_as_uint(K[(w*8 + g)*PSTR + ks*8 + t4 + 4]);
            #pragma unroll
            for (int m = 0; m < 2; m++) {
                uint32_t afr[4];
                int ab = (m*16 + g)*PSTR + ks*8 + t4;
                afr[0] = __float_as_uint(Qs[ab]);
                afr[1] = __float_as_uint(Qs[ab + 8*PSTR]);
                afr[2] = __float_as_uint(Qs[ab + 4]);
                afr[3] = __float_as_uint(Qs[ab + 8*PSTR + 4]);
                mma1688(s[m], afr, bfr);
            }
        }

        int tok0 = nc + w*8 + 2*t4;
        int tok1 = tok0 + 1;
        #pragma unroll
        for (int m = 0; m < 2; m++) {
            float e0 = __expf(s[m][0]), e1 = __expf(s[m][1]);
            float e2 = __expf(s[m][2]), e3 = __expf(s[m][3]);
            if (tok0 >= Ntok) { e0 = 0.f; e2 = 0.f; }
            if (tok1 >= Ntok) { e1 = 0.f; e3 = 0.f; }
            int r0 = m*16 + g, r1 = m*16 + g + 8;
            if (r0 < Tt) {
                size_t ob = ((size_t)bh*Tt + r0)*Ntok;
                if (tok0 < Ntok) out[ob + tok0] = e0;
                if (tok1 < Ntok) out[ob + tok1] = e1;
            }
            if (r1 < Tt) {
                size_t ob = ((size_t)bh*Tt + r1)*Ntok;
                if (tok0 < Ntok) out[ob + tok0] = e2;
                if (tok1 < Ntok) out[ob + tok1] = e3;
            }
            float r0s = e0 + e1, r1s = e2 + e3;
            r0s += __shfl_xor_sync(0xffffffffu, r0s, 1);
            r0s += __shfl_xor_sync(0xffffffffu, r0s, 2);
            r1s += __shfl_xor_sync(0xffffffffu, r1s, 1);
            r1s += __shfl_xor_sync(0xffffffffu, r1s, 2);
            if (t4 == 0) { ssum[m*2] += r0s; ssum[m*2 + 1] += r1s; }
        }
        __syncthreads();
    }

    if (t4 == 0) {
        ws[w*32 + g]      = ssum[0];
        ws[w*32 + g + 8]  = ssum[1];
        ws[w*32 + 16 + g] = ssum[2];
        ws[w*32 + 24 + g] = ssum[3];
    }
    __syncthreads();
    if (tid < Tt) {
        float s = 0.f;
        #pragma unroll
        for (int wq = 0; wq < 8; wq++) s += ws[wq*32 + tid];
        g_Fsum[((size_t)bh*NSEG + seg)*Tt + tid] = s;
    }

    __threadfence();
    __syncthreads();
    if (tid == 0) slast = atomicAdd(&g_cnt[bh], 1);
    __syncthreads();
    if (slast == NSEG - 1) {
        __threadfence();
        if (tid < Tt) {
            float S = 0.f;
            for (int sg = 0; sg < NSEG; sg++)
                S += g_Fsum[((size_t)bh*NSEG + sg)*Tt + tid];
            tinv[tid] = 1.f / S;
        }
        __syncthreads();
        size_t base = (size_t)bh*Tt*Ntok;
        for (int t = 0; t < Tt; t++) {
            float ti = tinv[t];
            size_t rb = base + (size_t)t*Ntok;
            for (int n = tid; n < Ntok; n += 256)
                out[rb + n] *= ti;
        }
    }
}

// ---------------- launch ----------------
extern "C" void kernel_launch(void* const* d_in, const int* in_sizes, int n_in,
                              void* d_out, int out_size) {
    const float* x       = (const float*)d_in[0];
    const float* ln1_g   = (const float*)d_in[1];
    const float* ln1_b   = (const float*)d_in[2];
    const float* kv0_w   = (const float*)d_in[3];
    const float* q0_w    = (const float*)d_in[4];
    const float* proj0_w = (const float*)d_in[5];
    const float* proj0_b = (const float*)d_in[6];
    const float* ln2_g   = (const float*)d_in[7];
    const float* ln2_b   = (const float*)d_in[8];
    const float* fc1_w   = (const float*)d_in[9];
    const float* fc1_b   = (const float*)d_in[10];
    const float* fc2_w   = (const float*)d_in[11];
    const float* fc2_b   = (const float*)d_in[12];
    const float* ln3_g   = (const float*)d_in[13];
    const float* ln3_b   = (const float*)d_in[14];
    const float* kv1_w   = (const float*)d_in[15];
    const float* q1_w    = (const float*)d_in[16];
    float* out = (float*)d_out;

    cudaFuncSetAttribute(k_gemm_mma, cudaFuncAttributeMaxDynamicSharedMemorySize, GEMM_SMEM);
    cudaFuncSetAttribute(k_attn0_mma, cudaFuncAttributeMaxDynamicSharedMemorySize, ATT_SMEM);

    k_prepstats<<<1536 + MTILES + Bq*Tt, 256>>>(x, kv0_w, kv1_w, q0_w,
                                                ln1_g, ln1_b, ln3_g, ln3_b);
    k_gemm_mma<<<dim3(12, MTILES), 256, GEMM_SMEM>>>();
    k_attn0_mma<<<dim3(Bq*Hh, NSEG), 256, ATT_SMEM>>>();
    k_cls<<<Bq*Tt, 512>>>(x, proj0_w, proj0_b, ln2_g, ln2_b,
                          fc1_w, fc1_b, fc2_w, fc2_b, ln3_g, ln3_b, kv1_w, q1_w);
    k_logits_mma<<<dim3(Bq*Hh, NSEG), 256>>>(out);
}

// round 17
// speedup vs baseline: 1.2551x; 1.0808x over previous
#include <cuda_runtime.h>
#include <cstdint>
#include <math.h>

#define Bq 8
#define Ntok 9237
#define Cc 512
#define Tt 21
#define Hh 8
#define Dd 64
#define HIDN 2048
#define M_ROWS (Bq*Ntok)          // 73896
#define EPSV 1e-5f
#define SCALEV 0.125f
#define NSEG 37                    // ceil(9237/256)
#define PSTR 72                    // smem row stride (floats): conflict-free frags
#define MTILES 578                 // ceil(73896/128)

// ---------------- static scratch (no allocations allowed) ----------------
__device__ __align__(16) float g_mean[M_ROWS];
__device__ __align__(16) float g_rstd[M_ROWS];
__device__ __align__(16) uint32_t g_Afrag[(size_t)MTILES*16*4096];  // LN'd A, tf32, fragment order
__device__ __align__(16) float g_Bfrag[1536*512];   // fragment-packed, gamma-folded, tf32
__device__ __align__(16) float g_biasc[1536];
__device__ __align__(16) float g_K0[(size_t)Bq*Hh*Ntok*Dd];
__device__ __align__(16) float g_V0[(size_t)Bq*Hh*Ntok*Dd];
__device__ __align__(16) float g_K1[(size_t)Bq*Hh*Ntok*Dd];
__device__ __align__(16) float g_q0[Bq*Tt*Cc];
__device__ __align__(16) float g_q1[Bq*Tt*Cc];
__device__ __align__(16) float g_Pacc[(size_t)Bq*Hh*NSEG*Tt*Dd];
__device__ __align__(16) float g_Psum[Bq*Hh*NSEG*Tt];
__device__ __align__(16) float g_Fsum[Bq*Hh*NSEG*Tt];
__device__ int g_cnt[Bq*Hh];

// ---------------- helpers ----------------
__device__ __forceinline__ uint32_t smem_u32(const void* p) {
    uint32_t a;
    asm("{ .reg .u64 t; cvta.to.shared.u64 t, %1; cvt.u32.u64 %0, t; }" : "=r"(a) : "l"(p));
    return a;
}
__device__ __forceinline__ uint32_t tf32r(float f) {
    uint32_t u; asm("cvt.rna.tf32.f32 %0, %1;" : "=r"(u) : "f"(f)); return u;
}
__device__ __forceinline__ void cp_async16(uint32_t smem, const void* g) {
    asm volatile("cp.async.cg.shared.global [%0], [%1], 16;" :: "r"(smem), "l"(g));
}
__device__ __forceinline__ void cp_async16z(uint32_t smem, const void* g, int szbytes) {
    asm volatile("cp.async.cg.shared.global [%0], [%1], 16, %2;"
                 :: "r"(smem), "l"(g), "r"(szbytes));
}
#define CP_COMMIT() asm volatile("cp.async.commit_group;" ::: "memory")
#define CP_WAIT0()  asm volatile("cp.async.wait_group 0;" ::: "memory")
#define CP_WAIT1()  asm volatile("cp.async.wait_group 1;" ::: "memory")

__device__ __forceinline__ void mma1688(float* c, const uint32_t* a, const uint32_t* b) {
    asm volatile(
        "mma.sync.aligned.m16n8k8.row.col.f32.tf32.tf32.f32 "
        "{%0,%1,%2,%3}, {%4,%5,%6,%7}, {%8,%9}, {%0,%1,%2,%3};"
        : "+f"(c[0]), "+f"(c[1]), "+f"(c[2]), "+f"(c[3])
        : "r"(a[0]), "r"(a[1]), "r"(a[2]), "r"(a[3]), "r"(b[0]), "r"(b[1]));
}

// ---------------- K1: prep (B frags) + LN stats + A frags + q0, one launch ----
__global__ __launch_bounds__(256) void k_prepstats(
        const float* __restrict__ x,
        const float* __restrict__ kv0_w, const float* __restrict__ kv1_w,
        const float* __restrict__ q0_w,
        const float* __restrict__ g1, const float* __restrict__ b1,
        const float* __restrict__ g3, const float* __restrict__ b3) {
    __shared__ float shbuf[128*33 + 256];
    int bid = blockIdx.x;
    int tid = threadIdx.x;
    if (bid < 1536) {
        int n = bid;
        const float *W, *g, *b; int col;
        if (n < 1024) { W = kv0_w; g = g1; b = b1; col = n; }
        else          { W = kv1_w; g = g3; b = b3; col = n - 1024; }
        int bx = n >> 7;
        int np = n & 127;
        int n8 = np >> 3, gg = np & 7;
        float partial = 0.f;
        for (int k = tid; k < 512; k += 256) {
            float w = W[(size_t)k*1024 + col] * g[k];
            int c  = k >> 5;
            int kc = k & 31;
            int ks = kc >> 3, kin = kc & 7;
            int t = kin & 3, reg = kin >> 2;
            int lane = gg*4 + t;
            size_t idx = (size_t)(bx*16 + c)*4096 + ((n8*4 + ks)*32 + lane)*2 + reg;
            g_Bfrag[idx] = __uint_as_float(tf32r(w));
            partial += b[k] * w;
        }
        float* red = shbuf;
        red[tid] = partial; __syncthreads();
        for (int s = 128; s; s >>= 1) {
            if (tid < s) red[tid] += red[tid + s];
            __syncthreads();
        }
        if (tid == 0) g_biasc[n] = red[0];
    } else if (bid < 1536 + MTILES) {
        float* ms = shbuf;
        float* rs = shbuf + 128;
        float* xs = shbuf + 256;
        int rowBase = (bid - 1536)*128;
        {
            int rl = tid >> 1;
            int row = rowBase + rl;
            int half = tid & 1;
            float s = 0.f, sq = 0.f;
            if (row < M_ROWS) {
                const float4* xr = (const float4*)(x + (size_t)row*512 + half*256);
                #pragma unroll 8
                for (int i = 0; i < 64; i++) {
                    float4 v = xr[i];
                    s  += v.x + v.y + v.z + v.w;
                    sq += v.x*v.x + v.y*v.y + v.z*v.z + v.w*v.w;
                }
            }
            s  += __shfl_xor_sync(0xffffffffu, s, 1);
            sq += __shfl_xor_sync(0xffffffffu, sq, 1);
            if (half == 0) {
                float m = s * (1.f/512.f);
                float var = sq * (1.f/512.f) - m*m;
                float rr = rsqrtf(var + EPSV);
                ms[rl] = m; rs[rl] = rr;
                if (row < M_ROWS) { g_mean[row] = m; g_rstd[row] = rr; }
            }
        }
        __syncthreads();
        uint32_t* dst = g_Afrag + (size_t)(bid - 1536)*16*4096;
        for (int c = 0; c < 16; c++) {
            #pragma unroll
            for (int it = 0; it < 4; it++) {
                int slot = tid + it*256;
                int row = slot >> 3, q = slot & 7;
                int r = rowBase + row;
                float4 v = (r < M_ROWS)
                    ? *(const float4*)(x + (size_t)r*512 + c*32 + q*4)
                    : make_float4(0,0,0,0);
                float* xp = &xs[row*33 + q*4];
                xp[0] = v.x; xp[1] = v.y; xp[2] = v.z; xp[3] = v.w;
            }
            __syncthreads();
            #pragma unroll
            for (int it = 0; it < 16; it++) {
                int f = tid + it*256;
                int reg = f & 3, lane = (f >> 2) & 31, ks = (f >> 7) & 3, mtile = f >> 9;
                int g = lane >> 2, t4 = lane & 3;
                int rl = mtile*16 + (reg & 1)*8 + g;
                int kl = ks*8 + t4 + (reg >> 1)*4;
                float v = (xs[rl*33 + kl] - ms[rl]) * rs[rl];
                dst[c*4096 + f] = tf32r(v);
            }
            __syncthreads();
        }
    } else {
        int r = bid - 1536 - MTILES;
        int b = r / Tt, t = r % Tt;
        int row = b*Ntok + t;
        float* y = shbuf;
        float* red2 = shbuf + 512;
        float v0 = x[(size_t)row*512 + tid];
        float v1 = x[(size_t)row*512 + tid + 256];
        float s = v0 + v1, sq = v0*v0 + v1*v1;
        for (int o = 16; o; o >>= 1) {
            s  += __shfl_down_sync(0xffffffffu, s, o);
            sq += __shfl_down_sync(0xffffffffu, sq, o);
        }
        int wid = tid >> 5, lane = tid & 31;
        if (lane == 0) { red2[wid] = s; red2[32 + wid] = sq; }
        __syncthreads();
        if (tid == 0) {
            float S = 0.f, SQ = 0.f;
            for (int w = 0; w < 8; w++) { S += red2[w]; SQ += red2[32 + w]; }
            float m = S * (1.f/512.f);
            red2[16] = m;
            red2[17] = rsqrtf(SQ * (1.f/512.f) - m*m + EPSV);
        }
        __syncthreads();
        float m = red2[16], rr = red2[17];
        float y0 = (v0 - m)*rr*g1[tid]       + b1[tid];
        float y1 = (v1 - m)*rr*g1[tid + 256] + b1[tid + 256];
        __syncthreads();
        y[tid] = y0;
        y[tid + 256] = y1;
        __syncthreads();
        // q0: float4-column GEMV, 2x k-split (256 each), 128 col-groups
        {
            int kh = tid >> 7;          // 0..1
            int cg = tid & 127;
            float a0 = 0.f, a1 = 0.f, a2 = 0.f, a3 = 0.f;
            int k0 = kh*256;
            for (int k = k0; k < k0 + 256; k++) {
                float yv = y[k];
                float4 wv = *(const float4*)(q0_w + (size_t)k*512 + cg*4);
                a0 = fmaf(yv, wv.x, a0); a1 = fmaf(yv, wv.y, a1);
                a2 = fmaf(yv, wv.z, a2); a3 = fmaf(yv, wv.w, a3);
            }
            float* part = shbuf + 1024;          // 2*512 floats
            part[kh*512 + cg*4 + 0] = a0;
            part[kh*512 + cg*4 + 1] = a1;
            part[kh*512 + cg*4 + 2] = a2;
            part[kh*512 + cg*4 + 3] = a3;
        }
        __syncthreads();
        {
            float* part = shbuf + 1024;
            #pragma unroll
            for (int oo = 0; oo < 2; oo++) {
                int o = tid + oo*256;
                g_q0[(size_t)r*512 + o] = part[o] + part[512 + o];
            }
        }
    }
}

// ---------------- K2: pure-stream tf32 mma GEMM (3-stage cp.async) ----------------
#define GEMM_SMEM (3*32768)

__global__ __launch_bounds__(256, 2) void k_gemm_mma() {
    extern __shared__ uint32_t dsmu[];

    const int tid = threadIdx.x;
    const int bx = blockIdx.x;
    const int by = blockIdx.y;
    const int colBase = bx * 128;
    const int rowBase = by * 128;

    const int lane = tid & 31, wid = tid >> 5;
    const int warp_m = wid & 1, warp_n = wid >> 1;
    const int g = lane >> 2, t4 = lane & 3;

    const uint32_t sbase = smem_u32(dsmu);
    const uint32_t* Asrc = g_Afrag + (size_t)by*16*4096;
    const uint32_t* Bsrc = (const uint32_t*)g_Bfrag + (size_t)bx*16*4096;

    auto issue = [&](int c, int s) {
        uint32_t dstA = sbase + (uint32_t)s*32768;
        const uint32_t* a = Asrc + c*4096;
        const uint32_t* b = Bsrc + c*4096;
        #pragma unroll
        for (int it = 0; it < 4; it++) {
            int off = (tid + it*256)*4;
            cp_async16(dstA + off*4, a + off);
            cp_async16(dstA + 16384 + off*4, b + off);
        }
        CP_COMMIT();
    };

    float acc[4][4][4];
    #pragma unroll
    for (int i = 0; i < 4; i++)
        #pragma unroll
        for (int j = 0; j < 4; j++)
            #pragma unroll
            for (int k = 0; k < 4; k++) acc[i][j][k] = 0.f;

    issue(0, 0); issue(1, 1);

    int s = 0;
    for (int c = 0; c < 16; c++) {
        CP_WAIT1();
        __syncthreads();
        if (c + 2 < 16) issue(c + 2, (c + 2) % 3);
        else CP_COMMIT();

        const uint32_t* Af = dsmu + s*8192;
        const uint32_t* Bf = dsmu + s*8192 + 4096;
        #pragma unroll
        for (int ks = 0; ks < 4; ks++) {
            uint32_t bfr[4][2];
            #pragma unroll
            for (int nf = 0; nf < 4; nf++) {
                int fi = (((warp_n*4 + nf)*4 + ks)*32 + lane)*2;
                uint2 bv = *(const uint2*)(Bf + fi);
                bfr[nf][0] = bv.x;
                bfr[nf][1] = bv.y;
            }
            #pragma unroll
            for (int mf = 0; mf < 4; mf++) {
                int ai = (((warp_m*4 + mf)*4 + ks)*32 + lane)*4;
                uint4 av = *(const uint4*)(Af + ai);
                uint32_t afr[4] = {av.x, av.y, av.z, av.w};
                #pragma unroll
                for (int nf = 0; nf < 4; nf++)
                    mma1688(acc[mf][nf], afr, bfr[nf]);
            }
        }
        s = (s == 2) ? 0 : s + 1;
    }

    const int region = bx >> 2;
    float* dstB = (region == 0) ? g_K0 : (region == 1) ? g_V0 : g_K1;
    float2 bias[4];
    #pragma unroll
    for (int nf = 0; nf < 4; nf++) {
        int j = colBase + warp_n*32 + nf*8 + t4*2;
        bias[nf] = *(const float2*)(g_biasc + j);
    }
    #pragma unroll
    for (int mf = 0; mf < 4; mf++) {
        #pragma unroll
        for (int hi = 0; hi < 2; hi++) {
            int r = rowBase + warp_m*64 + mf*16 + g + hi*8;
            if (r >= M_ROWS) continue;
            int bb = r / Ntok, nt = r % Ntok;
            #pragma unroll
            for (int nf = 0; nf < 4; nf++) {
                int j = colBase + warp_n*32 + nf*8 + t4*2;
                int h = (j >> 6) & 7, d = j & 63;
                float2 v;
                v.x = acc[mf][nf][hi*2 + 0] + bias[nf].x;
                v.y = acc[mf][nf][hi*2 + 1] + bias[nf].y;
                *(float2*)(dstB + (((size_t)bb*Hh + h)*Ntok + nt)*64 + d) = v;
            }
        }
    }
}

// ---------------- K3: attn0 via mma, double-buffered K/V chunk pipeline ----------
#define ATT_SMEM ((32*PSTR + 2*64*PSTR + 2*64*PSTR + 32*PSTR)*4 + 8*32*4)

__global__ __launch_bounds__(256) void k_attn0_mma() {
    extern __shared__ float sm[];
    float* Qs = sm;
    float* Ks = Qs + 32*PSTR;
    float* Vs = Ks + 2*64*PSTR;
    float* Ps = Vs + 2*64*PSTR;
    float* ws = Ps + 32*PSTR;

    int bh = blockIdx.x, seg = blockIdx.y;
    int b = bh >> 3, h = bh & 7;
    int tid = threadIdx.x;
    int lane = tid & 31, w = tid >> 5;
    int g = lane >> 2, t4 = lane & 3;

    for (int i = tid; i < 32*64; i += 256) {
        int t = i >> 6, d = i & 63;
        float v = (t < Tt) ? SCALEV * g_q0[(size_t)b*Tt*512 + h*(Tt*Dd) + t*Dd + d] : 0.f;
        Qs[t*PSTR + d] = __uint_as_float(tf32r(v));
    }

    const float* Kb = g_K0 + (size_t)bh*Ntok*64;
    const float* Vb = g_V0 + (size_t)bh*Ntok*64;
    uint32_t KsU = smem_u32(Ks), VsU = smem_u32(Vs);

    auto loadKV = [&](int ch, int buf) {
        int nc = seg*256 + ch*64;
        uint32_t kb = KsU + (uint32_t)buf*64*PSTR*4;
        uint32_t vb = VsU + (uint32_t)buf*64*PSTR*4;
        #pragma unroll
        for (int it = 0; it < 4; it++) {
            int slot = tid + it*256;
            int r = slot >> 4, c4 = (slot & 15)*4;
            int gn = nc + r;
            bool p = gn < Ntok;
            int gc = p ? gn : 0;
            int sz = p ? 16 : 0;
            cp_async16z(kb + (r*PSTR + c4)*4, Kb + (size_t)gc*64 + c4, sz);
            cp_async16z(vb + (r*PSTR + c4)*4, Vb + (size_t)gc*64 + c4, sz);
        }
        CP_COMMIT();
    };

    float o[2][4];
    #pragma unroll
    for (int m = 0; m < 2; m++)
        #pragma unroll
        for (int e = 0; e < 4; e++) o[m][e] = 0.f;
    float ssum[4] = {0.f, 0.f, 0.f, 0.f};

    loadKV(0, 0);
    for (int ch = 0; ch < 4; ch++) {
        if (ch < 3) loadKV(ch + 1, (ch + 1) & 1);
        if (ch < 3) { CP_WAIT1(); } else { CP_WAIT0(); }
        __syncthreads();

        int buf = ch & 1;
        const float* K = Ks + buf*64*PSTR;
        const float* V = Vs + buf*64*PSTR;
        int nc = seg*256 + ch*64;

        float s[2][4];
        #pragma unroll
        for (int m = 0; m < 2; m++)
            #pragma unroll
            for (int e = 0; e < 4; e++) s[m][e] = 0.f;
        #pragma unroll
        for (int ks = 0; ks < 8; ks++) {
            uint32_t bfr[2];
            bfr[0] = __float_as_uint(K[(w*8 + g)*PSTR + ks*8 + t4]);
            bfr[1] = __float_as_uint(K[(w*8 + g)*PSTR + ks*8 + t4 + 4]);
            #pragma unroll
            for (int m = 0; m < 2; m++) {
                uint32_t afr[4];
                int ab = (m*16 + g)*PSTR + ks*8 + t4;
                afr[0] = __float_as_uint(Qs[ab]);
                afr[1] = __float_as_uint(Qs[ab + 8*PSTR]);
                afr[2] = __float_as_uint(Qs[ab + 4]);
                afr[3] = __float_as_uint(Qs[ab + 8*PSTR + 4]);
                mma1688(s[m], afr, bfr);
            }
        }

        int tok0 = nc + w*8 + 2*t4;
        int tok1 = tok0 + 1;
        #pragma unroll
        for (int m = 0; m < 2; m++) {
            float e0 = __expf(s[m][0]), e1 = __expf(s[m][1]);
            float e2 = __expf(s[m][2]), e3 = __expf(s[m][3]);
            if (tok0 >= Ntok) { e0 = 0.f; e2 = 0.f; }
            if (tok1 >= Ntok) { e1 = 0.f; e3 = 0.f; }
            e0 = __uint_as_float(tf32r(e0)); e1 = __uint_as_float(tf32r(e1));
            e2 = __uint_as_float(tf32r(e2)); e3 = __uint_as_float(tf32r(e3));
            *(float2*)&Ps[(m*16 + g)*PSTR + w*8 + 2*t4]     = make_float2(e0, e1);
            *(float2*)&Ps[(m*16 + g + 8)*PSTR + w*8 + 2*t4] = make_float2(e2, e3);
            float r0 = e0 + e1, r1 = e2 + e3;
            r0 += __shfl_xor_sync(0xffffffffu, r0, 1);
            r0 += __shfl_xor_sync(0xffffffffu, r0, 2);
            r1 += __shfl_xor_sync(0xffffffffu, r1, 1);
            r1 += __shfl_xor_sync(0xffffffffu, r1, 2);
            if (t4 == 0) { ssum[m*2] += r0; ssum[m*2 + 1] += r1; }
        }
        __syncthreads();

        #pragma unroll
        for (int ks = 0; ks < 8; ks++) {
            uint32_t bfr[2];
            bfr[0] = __float_as_uint(V[(ks*8 + t4)*PSTR + w*8 + g]);
            bfr[1] = __float_as_uint(V[(ks*8 + t4 + 4)*PSTR + w*8 + g]);
            #pragma unroll
            for (int m = 0; m < 2; m++) {
                uint32_t afr[4];
                int ab = (m*16 + g)*PSTR + ks*8 + t4;
                afr[0] = __float_as_uint(Ps[ab]);
                afr[1] = __float_as_uint(Ps[ab + 8*PSTR]);
                afr[2] = __float_as_uint(Ps[ab + 4]);
                afr[3] = __float_as_uint(Ps[ab + 8*PSTR + 4]);
                mma1688(o[m], afr, bfr);
            }
        }
        __syncthreads();
    }

    if (t4 == 0) {
        ws[w*32 + g]      = ssum[0];
        ws[w*32 + g + 8]  = ssum[1];
        ws[w*32 + 16 + g] = ssum[2];
        ws[w*32 + 24 + g] = ssum[3];
    }
    __syncthreads();
    if (tid < Tt) {
        float s = 0.f;
        #pragma unroll
        for (int wq = 0; wq < 8; wq++) s += ws[wq*32 + tid];
        g_Psum[((size_t)bh*NSEG + seg)*Tt + tid] = s;
    }

    #pragma unroll
    for (int m = 0; m < 2; m++) {
        int r0 = m*16 + g, r1 = m*16 + g + 8;
        int d0 = w*8 + 2*t4;
        if (r0 < Tt)
            *(float2*)&g_Pacc[(((size_t)bh*NSEG + seg)*Tt + r0)*64 + d0] =
                make_float2(o[m][0], o[m][1]);
        if (r1 < Tt)
            *(float2*)&g_Pacc[(((size_t)bh*NSEG + seg)*Tt + r1)*64 + d0] =
                make_float2(o[m][2], o[m][3]);
    }
}

// ---------------- K4: cls path, 1024 threads, k-split float4 GEMVs ----------
__global__ __launch_bounds__(1024) void k_cls(const float* __restrict__ x,
        const float* __restrict__ proj0_w, const float* __restrict__ proj0_b,
        const float* __restrict__ g2, const float* __restrict__ b2,
        const float* __restrict__ fc1_w, const float* __restrict__ fc1_b,
        const float* __restrict__ fc2_w, const float* __restrict__ fc2_b,
        const float* __restrict__ g3, const float* __restrict__ b3,
        const float* __restrict__ kv1_w, const float* __restrict__ q1_w) {
    __shared__ float cer[512];
    __shared__ float cls[512];
    __shared__ float yb[512];
    __shared__ float hb[2048];
    __shared__ float part[4096];
    __shared__ float red[40];
    int tid = threadIdx.x;
    int r = blockIdx.x;
    int b = r / Tt, t = r % Tt;

    if (r == 0 && tid < Bq*Hh) g_cnt[tid] = 0;

    // ce inline (first 512 threads)
    if (tid < 512) {
        int h = tid >> 6, d = tid & 63;
        int bh = b*8 + h;
        float accv = 0.f, s = 0.f;
        for (int sg = 0; sg < NSEG; sg++) {
            accv += g_Pacc[(((size_t)bh*NSEG + sg)*Tt + t)*64 + d];
            s    += g_Psum[((size_t)bh*NSEG + sg)*Tt + t];
        }
        cer[tid] = accv / s;
    }
    __syncthreads();
    // proj0: 8x k-split (64 each), 128 col-groups of float4
    {
        int kq = tid >> 7, cg = tid & 127;
        float a0 = 0.f, a1 = 0.f, a2 = 0.f, a3 = 0.f;
        int k0 = kq*64;
        for (int k = k0; k < k0 + 64; k++) {
            float yv = cer[k];
            float4 wv = *(const float4*)(proj0_w + (size_t)k*512 + cg*4);
            a0 = fmaf(yv, wv.x, a0); a1 = fmaf(yv, wv.y, a1);
            a2 = fmaf(yv, wv.z, a2); a3 = fmaf(yv, wv.w, a3);
        }
        part[kq*512 + cg*4 + 0] = a0;
        part[kq*512 + cg*4 + 1] = a1;
        part[kq*512 + cg*4 + 2] = a2;
        part[kq*512 + cg*4 + 3] = a3;
    }
    __syncthreads();
    if (tid < 512) {
        float s = 0.f;
        #pragma unroll
        for (int j = 0; j < 8; j++) s += part[j*512 + tid];
        cls[tid] = x[((size_t)b*Ntok + t)*512 + tid] + s + proj0_b[tid];
    }
    __syncthreads();
    // LN2 (512-active form)
    {
        float v = 0.f, s = 0.f, sq = 0.f;
        if (tid < 512) {
            v = cls[tid]; s = v; sq = v*v;
            for (int o = 16; o; o >>= 1) {
                s  += __shfl_down_sync(0xffffffffu, s, o);
                sq += __shfl_down_sync(0xffffffffu, sq, o);
            }
            int wid = tid >> 5, lane = tid & 31;
            if (lane == 0) { red[wid] = s; red[16 + wid] = sq; }
        }
        __syncthreads();
        if (tid == 0) {
            float S = 0.f, SQ = 0.f;
            for (int w = 0; w < 16; w++) { S += red[w]; SQ += red[16 + w]; }
            float m = S * (1.f/512.f);
            red[32] = m;
            red[33] = rsqrtf(SQ * (1.f/512.f) - m*m + EPSV);
        }
        __syncthreads();
        if (tid < 512) yb[tid] = (v - red[32])*red[33]*g2[tid] + b2[tid];
    }
    __syncthreads();
    // fc1: 2x k-split (256 each), 512 col-groups of float4
    {
        int kh = tid >> 9, cg = tid & 511;
        float a0 = 0.f, a1 = 0.f, a2 = 0.f, a3 = 0.f;
        int k0 = kh*256;
        for (int k = k0; k < k0 + 256; k++) {
            float yv = yb[k];
            float4 wv = *(const float4*)(fc1_w + (size_t)k*2048 + cg*4);
            a0 = fmaf(yv, wv.x, a0); a1 = fmaf(yv, wv.y, a1);
            a2 = fmaf(yv, wv.z, a2); a3 = fmaf(yv, wv.w, a3);
        }
        part[kh*2048 + cg*4 + 0] = a0;
        part[kh*2048 + cg*4 + 1] = a1;
        part[kh*2048 + cg*4 + 2] = a2;
        part[kh*2048 + cg*4 + 3] = a3;
    }
    __syncthreads();
    #pragma unroll
    for (int oo = 0; oo < 2; oo++) {
        int o = tid + oo*1024;
        float a = part[o] + part[2048 + o] + fc1_b[o];
        hb[o] = 0.5f*a*(1.0f + erff(a*0.70710678118654752f));
    }
    __syncthreads();
    // fc2: 8x k-split (256 each), 128 col-groups of float4
    {
        int kq = tid >> 7, cg = tid & 127;
        float a0 = 0.f, a1 = 0.f, a2 = 0.f, a3 = 0.f;
        int k0 = kq*256;
        for (int k = k0; k < k0 + 256; k++) {
            float hv = hb[k];
            float4 wv = *(const float4*)(fc2_w + (size_t)k*512 + cg*4);
            a0 = fmaf(hv, wv.x, a0); a1 = fmaf(hv, wv.y, a1);
            a2 = fmaf(hv, wv.z, a2); a3 = fmaf(hv, wv.w, a3);
        }
        part[kq*512 + cg*4 + 0] = a0;
        part[kq*512 + cg*4 + 1] = a1;
        part[kq*512 + cg*4 + 2] = a2;
        part[kq*512 + cg*4 + 3] = a3;
    }
    __syncthreads();
    if (tid < 512) {
        float s = 0.f;
        #pragma unroll
        for (int j = 0; j < 8; j++) s += part[j*512 + tid];
        cls[tid] += s + fc2_b[tid];
    }
    __syncthreads();
    // LN3 (512-active form)
    {
        float v = 0.f, s = 0.f, sq = 0.f;
        if (tid < 512) {
            v = cls[tid]; s = v; sq = v*v;
            for (int o = 16; o; o >>= 1) {
                s  += __shfl_down_sync(0xffffffffu, s, o);
                sq += __shfl_down_sync(0xffffffffu, sq, o);
            }
            int wid = tid >> 5, lane = tid & 31;
            if (lane == 0) { red[wid] = s; red[16 + wid] = sq; }
        }
        __syncthreads();
        if (tid == 0) {
            float S = 0.f, SQ = 0.f;
            for (int w = 0; w < 16; w++) { S += red[w]; SQ += red[16 + w]; }
            float m = S * (1.f/512.f);
            red[32] = m;
            red[33] = rsqrtf(SQ * (1.f/512.f) - m*m + EPSV);
        }
        __syncthreads();
        if (tid < 512) yb[tid] = (v - red[32])*red[33]*g3[tid] + b3[tid];
    }
    __syncthreads();
    // k1 + q1 fused: 4x k-split (128 each); 256 col-groups (128 q1, 128 k1)
    {
        int kh = tid >> 8;            // 0..3
        int cg = tid & 255;           // 0..255
        const float* W;
        size_t stride;
        int col4;
        if (cg < 128) { W = q1_w;  stride = 512;  col4 = cg*4; }
        else          { W = kv1_w; stride = 1024; col4 = (cg - 128)*4; }
        float a0 = 0.f, a1 = 0.f, a2 = 0.f, a3 = 0.f;
        int k0 = kh*128;
        for (int k = k0; k < k0 + 128; k++) {
            float yv = yb[k];
            float4 wv = *(const float4*)(W + (size_t)k*stride + col4);
            a0 = fmaf(yv, wv.x, a0); a1 = fmaf(yv, wv.y, a1);
            a2 = fmaf(yv, wv.z, a2); a3 = fmaf(yv, wv.w, a3);
        }
        part[kh*1024 + cg*4 + 0] = a0;
        part[kh*1024 + cg*4 + 1] = a1;
        part[kh*1024 + cg*4 + 2] = a2;
        part[kh*1024 + cg*4 + 3] = a3;
    }
    __syncthreads();
    {
        int o = tid;                  // 0..1023
        float v = part[o] + part[1024 + o] + part[2048 + o] + part[3072 + o];
        if (o < 512) {
            g_q1[(size_t)r*512 + o] = v;
        } else {
            int col = o - 512;
            int h = col >> 6, d = col & 63;
            g_K1[(((size_t)b*Hh + h)*Ntok + t)*64 + d] = v;
        }
    }
}

// ---------------- K5: exp(logits) via mma + in-kernel finalize of softmax ----
__global__ __launch_bounds__(256) void k_logits_mma(float* __restrict__ out) {
    __shared__ float Qs[32*PSTR];
    __shared__ float Ks[2*64*PSTR];
    __shared__ float ws[8*32];
    __shared__ int slast;
    __shared__ float tinv[Tt];

    int bh = blockIdx.x, seg = blockIdx.y;
    int b = bh >> 3, h = bh & 7;
    int tid = threadIdx.x;
    int lane = tid & 31, w = tid >> 5;
    int g = lane >> 2, t4 = lane & 3;

    for (int i = tid; i < 32*64; i += 256) {
        int t = i >> 6, d = i & 63;
        float v = (t < Tt) ? SCALEV * g_q1[(size_t)b*Tt*512 + h*(Tt*Dd) + t*Dd + d] : 0.f;
        Qs[t*PSTR + d] = __uint_as_float(tf32r(v));
    }

    const float* Kb = g_K1 + (size_t)bh*Ntok*64;
    uint32_t KsU = smem_u32(Ks);
    float ssum[4] = {0.f, 0.f, 0.f, 0.f};

    auto loadK = [&](int ch, int buf) {
        int nc = seg*256 + ch*64;
        uint32_t kb = KsU + (uint32_t)buf*64*PSTR*4;
        #pragma unroll
        for (int it = 0; it < 2; it++) {
            int slot = tid + it*256;
            int r = slot >> 3, c8 = (slot & 7)*8;
            int gn = nc + r;
            bool p = gn < Ntok;
            int gc = p ? gn : 0;
            int sz = p ? 16 : 0;
            cp_async16z(kb + (r*PSTR + c8)*4,      Kb + (size_t)gc*64 + c8,     sz);
            cp_async16z(kb + (r*PSTR + c8 + 4)*4,  Kb + (size_t)gc*64 + c8 + 4, sz);
        }
        CP_COMMIT();
    };

    loadK(0, 0);
    for (int ch = 0; ch < 4; ch++) {
        if (ch < 3) loadK(ch + 1, (ch + 1) & 1);
        if (ch < 3) { CP_WAIT1(); } else { CP_WAIT0(); }
        __syncthreads();

        int buf = ch & 1;
        const float* K = Ks + buf*64*PSTR;
        int nc = seg*256 + ch*64;

        float s[2][4];
        #pragma unroll
        for (int m = 0; m < 2; m++)
            #pragma unroll
            for (int e = 0; e < 4; e++) s[m][e] = 0.f;
        #pragma unroll
        for (int ks = 0; ks < 8; ks++) {
            uint32_t bfr[2];
            bfr[0] = __float_as_uint(K[(w*8 + g)*PSTR + ks*8 + t4]);
            bfr[1] = __float_as_uint(K[(w*8 + g)*PSTR + ks*8 + t4 + 4]);
            #pragma unroll
            for (int m = 0; m < 2; m++) {
                uint32_t afr[4];
                int ab = (m*16 + g)*PSTR + ks*8 + t4;
                afr[0] = __float_as_uint(Qs[ab]);
                afr[1] = __float_as_uint(Qs[ab + 8*PSTR]);
                afr[2] = __float_as_uint(Qs[ab + 4]);
                afr[3] = __float_as_uint(Qs[ab + 8*PSTR + 4]);
                mma1688(s[m], afr, bfr);
            }
        }

        int tok0 = nc + w*8 + 2*t4;
        int tok1 = tok0 + 1;
        #pragma unroll
        for (int m = 0; m < 2; m++) {
            float e0 = __expf(s[m][0]), e1 = __expf(s[m][1]);
            float e2 = __expf(s[m][2]), e3 = __expf(s[m][3]);
            if (tok0 >= Ntok) { e0 = 0.f; e2 = 0.f; }
            if (tok1 >= Ntok) { e1 = 0.f; e3 = 0.f; }
            int r0 = m*16 + g, r1 = m*16 + g + 8;
            if (r0 < Tt) {
                size_t ob = ((size_t)bh*Tt + r0)*Ntok;
                if (tok0 < Ntok) out[ob + tok0] = e0;
                if (tok1 < Ntok) out[ob + tok1] = e1;
            }
            if (r1 < Tt) {
                size_t ob = ((size_t)bh*Tt + r1)*Ntok;
                if (tok0 < Ntok) out[ob + tok0] = e2;
                if (tok1 < Ntok) out[ob + tok1] = e3;
            }
            float r0s = e0 + e1, r1s = e2 + e3;
            r0s += __shfl_xor_sync(0xffffffffu, r0s, 1);
            r0s += __shfl_xor_sync(0xffffffffu, r0s, 2);
            r1s += __shfl_xor_sync(0xffffffffu, r1s, 1);
            r1s += __shfl_xor_sync(0xffffffffu, r1s, 2);
            if (t4 == 0) { ssum[m*2] += r0s; ssum[m*2 + 1] += r1s; }
        }
        __syncthreads();
    }

    if (t4 == 0) {
        ws[w*32 + g]      = ssum[0];
        ws[w*32 + g + 8]  = ssum[1];
        ws[w*32 + 16 + g] = ssum[2];
        ws[w*32 + 24 + g] = ssum[3];
    }
    __syncthreads();
    if (tid < Tt) {
        float s = 0.f;
        #pragma unroll
        for (int wq = 0; wq < 8; wq++) s += ws[wq*32 + tid];
        g_Fsum[((size_t)bh*NSEG + seg)*Tt + tid] = s;
    }

    __threadfence();
    __syncthreads();
    if (tid == 0) slast = atomicAdd(&g_cnt[bh], 1);
    __syncthreads();
    if (slast == NSEG - 1) {
        __threadfence();
        if (tid < Tt) {
            float S = 0.f;
            for (int sg = 0; sg < NSEG; sg++)
                S += g_Fsum[((size_t)bh*NSEG + sg)*Tt + tid];
            tinv[tid] = 1.f / S;
        }
        __syncthreads();
        size_t base = (size_t)bh*Tt*Ntok;
        for (int t = 0; t < Tt; t++) {
            float ti = tinv[t];
            size_t rb = base + (size_t)t*Ntok;
            for (int n = tid; n < Ntok; n += 256)
                out[rb + n] *= ti;
        }
    }
}

// ---------------- launch ----------------
extern "C" void kernel_launch(void* const* d_in, const int* in_sizes, int n_in,
                              void* d_out, int out_size) {
    const float* x       = (const float*)d_in[0];
    const float* ln1_g   = (const float*)d_in[1];
    const float* ln1_b   = (const float*)d_in[2];
    const float* kv0_w   = (const float*)d_in[3];
    const float* q0_w    = (const float*)d_in[4];
    const float* proj0_w = (const float*)d_in[5];
    const float* proj0_b = (const float*)d_in[6];
    const float* ln2_g   = (const float*)d_in[7];
    const float* ln2_b   = (const float*)d_in[8];
    const float* fc1_w   = (const float*)d_in[9];
    const float* fc1_b   = (const float*)d_in[10];
    const float* fc2_w   = (const float*)d_in[11];
    const float* fc2_b   = (const float*)d_in[12];
    const float* ln3_g   = (const float*)d_in[13];
    const float* ln3_b   = (const float*)d_in[14];
    const float* kv1_w   = (const float*)d_in[15];
    const float* q1_w    = (const float*)d_in[16];
    float* out = (float*)d_out;

    cudaFuncSetAttribute(k_gemm_mma, cudaFuncAttributeMaxDynamicSharedMemorySize, GEMM_SMEM);
    cudaFuncSetAttribute(k_attn0_mma, cudaFuncAttributeMaxDynamicSharedMemorySize, ATT_SMEM);

    k_prepstats<<<1536 + MTILES + Bq*Tt, 256>>>(x, kv0_w, kv1_w, q0_w,
                                                ln1_g, ln1_b, ln3_g, ln3_b);
    k_gemm_mma<<<dim3(12, MTILES), 256, GEMM_SMEM>>>();
    k_attn0_mma<<<dim3(Bq*Hh, NSEG), 256, ATT_SMEM>>>();
    k_cls<<<Bq*Tt, 1024>>>(x, proj0_w, proj0_b, ln2_g, ln2_b,
                           fc1_w, fc1_b, fc2_w, fc2_b, ln3_g, ln3_b, kv1_w, q1_w);
    k_logits_mma<<<dim3(Bq*Hh, NSEG), 256>>>(out);
}